// round 11
// baseline (speedup 1.0000x reference)
#include <cuda_runtime.h>
#include <cuda_fp16.h>
#include <math.h>

#define SS 2048
#define HH 16
#define DM 1024
#define DH 192
#define NQKV 9216
#define DL 3072
#define BHN 32
#define MROWS 4096

// Scratch (device globals: no allocation allowed)
__device__ __half   g_hh[MROWS * DH];             // 1.5 MB half
// Q in A-fragment tile layout: [bh][tile64(32)][12ks][4ms][128]  (u32 = half2)
__device__ unsigned g_qf[BHN * 32 * 6144];        // 25 MB
// K in B-fragment tile layout: [bh][tile64(32)][12ks][8ns][64]
__device__ unsigned g_kf[BHN * 32 * 6144];        // 25 MB
// V in B-fragment tile layout (k=j, n=d): [bh][tile64(32)][4ks][24ns][64]
__device__ unsigned g_vf[BHN * 32 * 6144];        // 25 MB
// O in A-fragment tile layout: [b(2)][mt(16)][kc(48)][4ks][8ms][128]
__device__ unsigned g_attnf[2 * 16 * 48 * 4096];  // 25 MB
// w_up prepacked half B-frag: [nb(72)][12ks][16ns][64]
__device__ unsigned g_wu[72 * 12288];             // 3.5 MB
// w_o prepacked half B-frag: [nb(8)][kc(48)][4ks][16ns][64]
__device__ unsigned g_wo[8 * 48 * 4096];          // 6.3 MB

// ---------------------------------------------------------------------------
// f16 mma helpers (mma.sync m16n8k16, row.col, f32 accumulate)
//  A (16x16): (m,kp) -> [ks=k>>4][ms=m>>4][lane=(m&7)*4+(kp&3)][reg=((k&15)>=8)*2+((m&15)>=8)]
//  B (16x8):  (kp,n) -> [ks][ns=n>>3][lane=(n&7)*4+(kp&3)][reg=((k&15)>=8)]
//  Physical lane XOR-swizzled by slab: SW(lane, slab).
// ---------------------------------------------------------------------------
#define SW(l, s) ((l) ^ (((s) & 3) << 2))

__device__ __forceinline__ unsigned pack2(float a, float b) {
    __half2 h = __floats2half2_rn(a, b);
    return *(unsigned*)&h;
}

__device__ __forceinline__ void mma16(float4& d, const uint4& a, const uint2& b) {
    asm volatile("mma.sync.aligned.m16n8k16.row.col.f32.f16.f16.f32 "
                 "{%0,%1,%2,%3}, {%4,%5,%6,%7}, {%8,%9}, {%0,%1,%2,%3};\n"
                 : "+f"(d.x), "+f"(d.y), "+f"(d.z), "+f"(d.w)
                 : "r"(a.x), "r"(a.y), "r"(a.z), "r"(a.w), "r"(b.x), "r"(b.y));
}

__device__ __forceinline__ void cpa16(void* smem, const void* gmem) {
    unsigned sa = (unsigned)__cvta_generic_to_shared(smem);
    asm volatile("cp.async.cg.shared.global [%0], [%1], 16;" :: "r"(sa), "l"(gmem));
}
#define CP_COMMIT() asm volatile("cp.async.commit_group;")
#define CP_WAIT0()  asm volatile("cp.async.wait_group 0;")

// ---------------------------------------------------------------------------
// Kernel 1: h = rmsnorm(x @ w_down) * rms_w   -> g_hh (half)
// ---------------------------------------------------------------------------
__global__ void k_down_rms(const float* __restrict__ x,
                           const float* __restrict__ w_down,
                           const float* __restrict__ rms_w) {
    extern __shared__ float sm[];
    float* xs  = sm;                  // 16*1024
    float* red = sm + 16 * 1024;      // 16*192
    float* rs  = red + 16 * 192;      // 16

    int t  = threadIdx.x;             // 0..191
    int m0 = blockIdx.x * 16;

    const float4* xin = (const float4*)(x + (size_t)m0 * DM);
    float4* xs4 = (float4*)xs;
    for (int i = t; i < 16 * DM / 4; i += 192) xs4[i] = xin[i];
    __syncthreads();

    float acc[16];
#pragma unroll
    for (int r = 0; r < 16; r++) acc[r] = 0.f;

    for (int k = 0; k < DM; k += 4) {
        float w0 = w_down[(k + 0) * DH + t];
        float w1 = w_down[(k + 1) * DH + t];
        float w2 = w_down[(k + 2) * DH + t];
        float w3 = w_down[(k + 3) * DH + t];
#pragma unroll
        for (int r = 0; r < 16; r++) {
            float4 xv = *(const float4*)&xs[r * DM + k];
            acc[r] += xv.x * w0 + xv.y * w1 + xv.z * w2 + xv.w * w3;
        }
    }

#pragma unroll
    for (int r = 0; r < 16; r++) red[r * 192 + t] = acc[r] * acc[r];
    __syncthreads();
    for (int st = 96; st >= 3; st >>= 1) {
        if (t < st) {
#pragma unroll
            for (int r = 0; r < 16; r++) red[r * 192 + t] += red[r * 192 + t + st];
        }
        __syncthreads();
    }
    if (t < 16) {
        float s3 = red[t * 192 + 0] + red[t * 192 + 1] + red[t * 192 + 2];
        rs[t] = rsqrtf(s3 / 192.0f + 1e-6f);
    }
    __syncthreads();

    float w = rms_w[t];
#pragma unroll
    for (int r = 0; r < 16; r++)
        g_hh[(size_t)(m0 + r) * DH + t] = __float2half(acc[r] * rs[r] * w);
}

// ---------------------------------------------------------------------------
// Prepack kernels: weights -> half B-fragment tile layout (run per launch)
// ---------------------------------------------------------------------------
__global__ void k_pack_wup(const float* __restrict__ w_up) {
    int idx = blockIdx.x * 256 + threadIdx.x;     // 96*9216
    if (idx >= 96 * NQKV) return;
    int kp = idx / NQKV, n = idx % NQKV;
    int k = kp * 2;
    float v0 = w_up[(size_t)k * NQKV + n];
    float v1 = w_up[(size_t)(k + 1) * NQKV + n];
    int nb = n >> 7, nn = n & 127;
    int ks = k >> 4, reg = ((k & 15) >= 8) ? 1 : 0, c = (k & 7) >> 1;
    int ns = nn >> 3, l = (nn & 7) * 4 + c;
    g_wu[(size_t)nb * 12288 + (ks * 16 + ns) * 64 + SW(l, ns) * 2 + reg] = pack2(v0, v1);
}

__global__ void k_pack_wo(const float* __restrict__ w_o) {
    int idx = blockIdx.x * 256 + threadIdx.x;     // 1536*1024
    if (idx >= 1536 * 1024) return;
    int kp = idx >> 10, n = idx & 1023;
    int k = kp * 2;
    float v0 = w_o[(size_t)k * DM + n];
    float v1 = w_o[(size_t)(k + 1) * DM + n];
    int kc = k >> 6, kk = k & 63;
    int ks = kk >> 4, reg = ((kk & 15) >= 8) ? 1 : 0, c = (kk & 7) >> 1;
    int nb = n >> 7, nn = n & 127;
    int ns = nn >> 3, l = (nn & 7) * 4 + c;
    g_wo[(size_t)(nb * 48 + kc) * 4096 + (ks * 16 + ns) * 64 + SW(l, ns) * 2 + reg]
        = pack2(v0, v1);
}

// ---------------------------------------------------------------------------
// Kernel 2: qkv = h @ w_up (f16 mma). BM=128, BN=128, K=192. 256 threads,
// 8 warps 2(m) x 4(n); warp 64x32. B tile = raw cp.async copy of g_wu.
// RoPE fused into the epilogue. Q/K/V written in fragment-tile layout.
// ---------------------------------------------------------------------------
#define QKV_SMEM ((12 * 8 * 128 + 12 * 16 * 64) * 4)   // 98304 B
__global__ void __launch_bounds__(256, 2) k_qkv_mma() {
    extern __shared__ unsigned smu[];
    unsigned* Af = smu;                   // [12][8][128]
    unsigned* Bf = smu + 12288;           // [12][16][64]

    int tid = threadIdx.x, lane = tid & 31, warp = tid >> 5;
    int wm = warp >> 2, wn = warp & 3;
    int m0 = blockIdx.x * 128;
    int nb = blockIdx.y;                  // 0..71

    // B: raw async copy of prepacked w_up block
    {
        const uint4* wsrc = (const uint4*)(g_wu + (size_t)nb * 12288);
        uint4* Bd = (uint4*)Bf;
#pragma unroll
        for (int i = 0; i < 12; i++) cpa16(Bd + tid + i * 256, wsrc + tid + i * 256);
        CP_COMMIT();
    }
    // A: 128x192 halves of g_hh -> A-frag (k-pairs native)
    for (int i = tid; i < 128 * 48; i += 256) {
        int m = i / 48, k4 = (i % 48) * 4;
        uint2 v = *(const uint2*)&g_hh[(size_t)(m0 + m) * DH + k4];
        int ks = k4 >> 4, ms = m >> 4;
        int reg = (((k4 & 15) >= 8) ? 2 : 0) + (((m & 15) >= 8) ? 1 : 0);
        int l0 = (m & 7) * 4 + ((k4 >> 1) & 3);
        unsigned* base = &Af[(ks * 8 + ms) * 128];
        base[SW(l0, ms) * 4 + reg]     = v.x;
        base[SW(l0 + 1, ms) * 4 + reg] = v.y;
    }
    CP_WAIT0();
    __syncthreads();

    float4 acc[4][4];
#pragma unroll
    for (int im = 0; im < 4; im++)
#pragma unroll
        for (int in = 0; in < 4; in++) acc[im][in] = make_float4(0.f, 0.f, 0.f, 0.f);

#pragma unroll
    for (int ks = 0; ks < 12; ks++) {
        uint4 a[4];
#pragma unroll
        for (int im = 0; im < 4; im++) {
            int ms = wm * 4 + im;
            a[im] = *(const uint4*)&Af[(ks * 8 + ms) * 128 + SW(lane, ms) * 4];
        }
        uint2 b[4];
#pragma unroll
        for (int in = 0; in < 4; in++) {
            int ns = wn * 4 + in;
            b[in] = *(const uint2*)&Bf[(ks * 16 + ns) * 64 + SW(lane, ns) * 2];
        }
#pragma unroll
        for (int im = 0; im < 4; im++)
#pragma unroll
            for (int in = 0; in < 4; in++) mma16(acc[im][in], a[im], b[in]);
    }

    int b_ = m0 >> 11;
    int s0 = m0 & 2047;
#pragma unroll
    for (int im = 0; im < 4; im++)
#pragma unroll
        for (int h = 0; h < 2; h++) {
            int m = wm * 64 + im * 16 + h * 8 + (lane >> 2);
            int s = s0 + m;
            int tile = s >> 6, mrow = s & 63;
#pragma unroll
            for (int in2 = 0; in2 < 2; in2++)
#pragma unroll
                for (int cc = 0; cc < 2; cc++) {
                    float vlo, vhi;
                    if (h) { vlo = cc ? acc[im][in2].w : acc[im][in2].z;
                             vhi = cc ? acc[im][in2 + 2].w : acc[im][in2 + 2].z; }
                    else   { vlo = cc ? acc[im][in2].y : acc[im][in2].x;
                             vhi = cc ? acc[im][in2 + 2].y : acc[im][in2 + 2].x; }
                    int n = nb * 128 + wn * 32 + in2 * 8 + 2 * (lane & 3) + cc;
                    int ten = n / 3072;
                    int l = n % 3072;
                    int h_ = l & 15, d = l >> 4;     // d even; pair (d, d+1)
                    int bh = b_ * HH + h_;
                    // fused partial RoPE on q/k for d in [128,160)
                    if (ten != 2 && (unsigned)(d - 128) < 32u) {
                        int p = (d - 128) >> 1;
                        float inv = exp2f(-(float)p * 0.8304820237218406f); // log2(1e4)/16
                        float ang = (float)s * inv;
                        float sn, cs;
                        sincosf(ang, &sn, &cs);
                        float t0 = vlo * cs - vhi * sn;
                        vhi = vhi * cs + vlo * sn;
                        vlo = t0;
                    }
                    if (ten == 2) {
                        // V: B-frag (k=j sequence, n=d); halves stored individually
                        int j = mrow;
                        size_t base = (size_t)(bh * 32 + tile) * 6144;
                        int ksv = j >> 4;
                        int regv = ((j & 15) >= 8) ? 1 : 0;
                        int cv = (j >> 1) & 3;
                        int ns0 = d >> 3;
                        int lf0 = (d & 7) * 4 + cv;
                        __half* vh = (__half*)g_vf;
                        vh[(base + (ksv * 24 + ns0) * 64 + SW(lf0, ns0) * 2 + regv) * 2 + (j & 1)]
                            = __float2half(vlo);
                        vh[(base + (ksv * 24 + ns0) * 64 + SW(lf0 + 4, ns0) * 2 + regv) * 2 + (j & 1)]
                            = __float2half(vhi);
                    } else {
                        unsigned w = pack2(vlo, vhi);
                        int ks = d >> 4, c = (d & 7) >> 1;
                        int lf = (mrow & 7) * 4 + c;
                        if (ten == 0) {      // Q: A-frag
                            int ms = mrow >> 4;
                            int reg = (((d & 15) >= 8) ? 2 : 0) + (((mrow & 15) >= 8) ? 1 : 0);
                            g_qf[(size_t)(bh * 32 + tile) * 6144 +
                                 (ks * 4 + ms) * 128 + SW(lf, ms) * 4 + reg] = w;
                        } else {             // K: B-frag
                            int ns = mrow >> 3;
                            int reg = ((d & 15) >= 8) ? 1 : 0;
                            g_kf[(size_t)(bh * 32 + tile) * 6144 +
                                 (ks * 8 + ns) * 64 + SW(lf, ns) * 2 + reg] = w;
                        }
                    }
                }
        }
}

// ---------------------------------------------------------------------------
// Kernel 4: causal flash attention, warp-owns-full-rows design. 256 threads,
// 8 warps x 16 rows (Q tile 128). Softmax fully warp-local (registers +
// quad shuffles); P accumulators convert IN REGISTERS to PV A-fragments
// (C-layout == A-layout identity). 1 barrier per tile. K/V double-buffered
// cp.async raw copies of fragment-layout gmem.
// ---------------------------------------------------------------------------
#define ATT_SMEM ((12288 + 6144 * 2 + 6144 * 2) * 4)   // 147456 B
__global__ void __launch_bounds__(256, 1) k_attn_mma() {
    extern __shared__ unsigned smu[];
    unsigned* Qf = smu;             // [2 half][12ks][4ms][128]
    unsigned* Kf = smu + 12288;     // 2 x [12ks][8ns][64]
    unsigned* Vf = smu + 24576;     // 2 x [4ks][24ns][64]

    int tid = threadIdx.x, lane = tid & 31, warp = tid >> 5;   // warp 0..7
    int bh = blockIdx.y;
    int it = 15 - blockIdx.x;              // longest tiles first
    int i0 = it * 128;

    // prefetch Q (two contiguous 64-row frag tiles = 3072 uint4) + K/V tile 0
    {
        const uint4* qt4 = (const uint4*)(g_qf + (size_t)(bh * 32 + it * 2) * 6144);
        const uint4* kt4 = (const uint4*)(g_kf + (size_t)(bh * 32) * 6144);
        const uint4* vt4 = (const uint4*)(g_vf + (size_t)(bh * 32) * 6144);
        uint4* Qd = (uint4*)Qf;
        uint4* Kd = (uint4*)Kf;
        uint4* Vd = (uint4*)Vf;
#pragma unroll
        for (int i = 0; i < 12; i++) cpa16(Qd + tid + i * 256, qt4 + tid + i * 256);
#pragma unroll
        for (int i = 0; i < 6; i++) {
            cpa16(Kd + tid + i * 256, kt4 + tid + i * 256);
            cpa16(Vd + tid + i * 256, vt4 + tid + i * 256);
        }
        CP_COMMIT();
    }

    float4 o[24];
#pragma unroll
    for (int nf = 0; nf < 24; nf++) o[nf] = make_float4(0.f, 0.f, 0.f, 0.f);
    float rm0 = -3.0e38f, rm1 = -3.0e38f, rl0 = 0.f, rl1 = 0.f;

    const float scale = 0.07216878364870323f;   // 1/sqrt(192)
    int ntile = 2 * it + 2;
    int qbase = (warp >> 2) * 6144;
    int msl = warp & 3;
    int r0 = warp * 16 + (lane >> 2);

    for (int jt = 0; jt < ntile; jt++) {
        int kb = (jt & 1) * 6144;
        bool diag = (jt >= 2 * it);
        int off = jt * 64 - i0;

        CP_WAIT0();
        __syncthreads();                     // tile ready; prev compute done

        if (jt + 1 < ntile) {
            const uint4* kt4 = (const uint4*)(g_kf + (size_t)(bh * 32 + jt + 1) * 6144);
            const uint4* vt4 = (const uint4*)(g_vf + (size_t)(bh * 32 + jt + 1) * 6144);
            uint4* Kd = (uint4*)(Kf + (kb ^ 6144));
            uint4* Vd = (uint4*)(Vf + (kb ^ 6144));
#pragma unroll
            for (int i = 0; i < 6; i++) {
                cpa16(Kd + tid + i * 256, kt4 + tid + i * 256);
                cpa16(Vd + tid + i * 256, vt4 + tid + i * 256);
            }
        }
        CP_COMMIT();

        // S = Q K^T : warp computes 16 rows x 64 cols
        float4 s[8];
#pragma unroll
        for (int in = 0; in < 8; in++) s[in] = make_float4(0.f, 0.f, 0.f, 0.f);

#pragma unroll
        for (int ks = 0; ks < 12; ks++) {
            uint4 a = *(const uint4*)&Qf[qbase + (ks * 4 + msl) * 128 + SW(lane, msl) * 4];
#pragma unroll
            for (int in = 0; in < 8; in++) {
                uint2 b = *(const uint2*)&Kf[kb + (ks * 8 + in) * 64 + SW(lane, in) * 2];
                mma16(s[in], a, b);
            }
        }

        // scale + causal mask + warp-local row max (quad shuffles)
        float mx0 = -3.0e38f, mx1 = -3.0e38f;
#pragma unroll
        for (int in = 0; in < 8; in++) {
            float4& sv = s[in];
            sv.x *= scale; sv.y *= scale; sv.z *= scale; sv.w *= scale;
            if (diag) {
                int col = off + in * 8 + 2 * (lane & 3);
                if (col > r0)         sv.x = -1e9f;
                if (col + 1 > r0)     sv.y = -1e9f;
                if (col > r0 + 8)     sv.z = -1e9f;
                if (col + 1 > r0 + 8) sv.w = -1e9f;
            }
            mx0 = fmaxf(mx0, fmaxf(sv.x, sv.y));
            mx1 = fmaxf(mx1, fmaxf(sv.z, sv.w));
        }
        mx0 = fmaxf(mx0, __shfl_xor_sync(0xffffffffu, mx0, 1));
        mx0 = fmaxf(mx0, __shfl_xor_sync(0xffffffffu, mx0, 2));
        mx1 = fmaxf(mx1, __shfl_xor_sync(0xffffffffu, mx1, 1));
        mx1 = fmaxf(mx1, __shfl_xor_sync(0xffffffffu, mx1, 2));
        float mn0 = fmaxf(rm0, mx0), mn1 = fmaxf(rm1, mx1);
        float c0 = __expf(rm0 - mn0), c1 = __expf(rm1 - mn1);
        rm0 = mn0; rm1 = mn1;

        // exp in registers -> PV A-fragments directly (C-layout == A-layout)
        uint4 pa[4];
        float sum0 = 0.f, sum1 = 0.f;
#pragma unroll
        for (int kp = 0; kp < 4; kp++) {
            float e0x = __expf(s[2 * kp].x - mn0),     e0y = __expf(s[2 * kp].y - mn0);
            float e0z = __expf(s[2 * kp].z - mn1),     e0w = __expf(s[2 * kp].w - mn1);
            float e1x = __expf(s[2 * kp + 1].x - mn0), e1y = __expf(s[2 * kp + 1].y - mn0);
            float e1z = __expf(s[2 * kp + 1].z - mn1), e1w = __expf(s[2 * kp + 1].w - mn1);
            sum0 += e0x + e0y + e1x + e1y;
            sum1 += e0z + e0w + e1z + e1w;
            pa[kp].x = pack2(e0x, e0y);   // (row,   k lo)
            pa[kp].y = pack2(e0z, e0w);   // (row+8, k lo)
            pa[kp].z = pack2(e1x, e1y);   // (row,   k hi)
            pa[kp].w = pack2(e1z, e1w);   // (row+8, k hi)
        }
        sum0 += __shfl_xor_sync(0xffffffffu, sum0, 1);
        sum0 += __shfl_xor_sync(0xffffffffu, sum0, 2);
        sum1 += __shfl_xor_sync(0xffffffffu, sum1, 1);
        sum1 += __shfl_xor_sync(0xffffffffu, sum1, 2);
        rl0 = rl0 * c0 + sum0;
        rl1 = rl1 * c1 + sum1;

        // rescale O, then O += P @ V  (warp: 16 rows x 192 d)
#pragma unroll
        for (int nf = 0; nf < 24; nf++) {
            o[nf].x *= c0; o[nf].y *= c0; o[nf].z *= c1; o[nf].w *= c1;
        }
#pragma unroll
        for (int kp = 0; kp < 4; kp++) {
#pragma unroll
            for (int nf = 0; nf < 24; nf++) {
                uint2 b = *(const uint2*)&Vf[kb + (kp * 24 + nf) * 64 + SW(lane, nf) * 2];
                mma16(o[nf], pa[kp], b);
            }
        }
    }

    // epilogue: normalize, write O in A-frag tile layout (g_attnf)
    float inv0 = 1.f / rl0, inv1 = 1.f / rl1;
    int b_ = bh >> 4, h_ = bh & 15;
    size_t tb = (size_t)(b_ * 16 + it) * 48 * 4096;
    int ms = warp;
#pragma unroll
    for (int nf = 0; nf < 24; nf++) {
        int d = nf * 8 + 2 * (lane & 3);
        int l = h_ * 192 + d;
        int kc = l >> 6, kk = l & 63;
        int ks = kk >> 4;
        int regk = ((kk & 15) >= 8) ? 2 : 0;
        int c = (kk >> 1) & 3;
        int lw = (lane >> 2) * 4 + c;
        unsigned* dst = &g_attnf[tb + ((kc * 4 + ks) * 8 + ms) * 128 + SW(lw, ms) * 4 + regk];
        dst[0] = pack2(o[nf].x * inv0, o[nf].y * inv0);    // rows r (regm 0)
        dst[1] = pack2(o[nf].z * inv1, o[nf].w * inv1);    // rows r+8 (regm 1)
    }
}

// ---------------------------------------------------------------------------
// Kernel 5: out = O @ w_o  (f16 mma)  [4096,3072]@[3072,1024]
// BM=128, BN=128, BK=64, 48 chunks, double-buffered cp.async raw copies
// (A from g_attnf frag tiles, B from g_wo prepack). 8 warps 4m x 2n.
// ---------------------------------------------------------------------------
#define OUT_SMEM (2 * (4096 + 4096) * 4)   // 65536 B
__global__ void __launch_bounds__(256, 2) k_out_mma(float* __restrict__ out) {
    extern __shared__ unsigned smu[];
    unsigned* Af = smu;          // 2 x [4ks][8ms][128]
    unsigned* Bf = smu + 8192;   // 2 x [4ks][16ns][64]

    int tid = threadIdx.x, lane = tid & 31, warp = tid >> 5;
    int wm = warp >> 1, wn = warp & 1;
    int m0 = blockIdx.x * 128;
    int b_ = m0 >> 11, mt = (m0 >> 7) & 15;
    int nb = blockIdx.y;
    int n0 = nb * 128;

    const uint4* asrc = (const uint4*)(g_attnf + (size_t)(b_ * 16 + mt) * 48 * 4096);
    const uint4* bsrc = (const uint4*)(g_wo + (size_t)nb * 48 * 4096);

    {
        uint4* Ad = (uint4*)Af;
        uint4* Bd = (uint4*)Bf;
#pragma unroll
        for (int i = 0; i < 4; i++) {
            cpa16(Ad + tid + i * 256, asrc + tid + i * 256);
            cpa16(Bd + tid + i * 256, bsrc + tid + i * 256);
        }
        CP_COMMIT();
    }

    float4 acc[2][8];
#pragma unroll
    for (int im = 0; im < 2; im++)
#pragma unroll
        for (int in = 0; in < 8; in++) acc[im][in] = make_float4(0.f, 0.f, 0.f, 0.f);

    for (int kc = 0; kc < 48; kc++) {
        int boff = (kc & 1) * 4096;
        CP_WAIT0();
        __syncthreads();

        if (kc + 1 < 48) {
            int nboff = ((kc + 1) & 1) * 1024;
            uint4* Ad = (uint4*)Af + nboff;
            uint4* Bd = (uint4*)Bf + nboff;
            const uint4* an = asrc + (kc + 1) * 1024;
            const uint4* bn = bsrc + (kc + 1) * 1024;
#pragma unroll
            for (int i = 0; i < 4; i++) {
                cpa16(Ad + tid + i * 256, an + tid + i * 256);
                cpa16(Bd + tid + i * 256, bn + tid + i * 256);
            }
        }
        CP_COMMIT();

#pragma unroll
        for (int ks = 0; ks < 4; ks++) {
            uint4 a0 = *(const uint4*)&Af[boff + (ks * 8 + wm * 2 + 0) * 128 + SW(lane, wm * 2) * 4];
            uint4 a1 = *(const uint4*)&Af[boff + (ks * 8 + wm * 2 + 1) * 128 + SW(lane, wm * 2 + 1) * 4];
            uint2 b[8];
#pragma unroll
            for (int in = 0; in < 8; in++) {
                int ns = wn * 8 + in;
                b[in] = *(const uint2*)&Bf[boff + (ks * 16 + ns) * 64 + SW(lane, ns) * 2];
            }
#pragma unroll
            for (int in = 0; in < 8; in++) { mma16(acc[0][in], a0, b[in]); mma16(acc[1][in], a1, b[in]); }
        }
    }

#pragma unroll
    for (int im = 0; im < 2; im++)
#pragma unroll
        for (int h = 0; h < 2; h++) {
            int m = m0 + wm * 32 + im * 16 + h * 8 + (lane >> 2);
#pragma unroll
            for (int in = 0; in < 8; in++) {
                int n = n0 + wn * 64 + in * 8 + 2 * (lane & 3);
                float2 v;
                v.x = h ? acc[im][in].z : acc[im][in].x;
                v.y = h ? acc[im][in].w : acc[im][in].y;
                *(float2*)&out[(size_t)m * DM + n] = v;
            }
        }
}

// ---------------------------------------------------------------------------
extern "C" void kernel_launch(void* const* d_in, const int* in_sizes, int n_in,
                              void* d_out, int out_size) {
    (void)in_sizes; (void)n_in; (void)out_size;
    const float* x      = (const float*)d_in[0];
    // d_in[1] = mask (int32 tril) — causality applied analytically, ignored
    const float* w_down = (const float*)d_in[2];
    const float* rms_w  = (const float*)d_in[3];
    const float* w_up   = (const float*)d_in[4];
    const float* w_o    = (const float*)d_in[5];
    float* out = (float*)d_out;

    cudaFuncSetAttribute(k_down_rms, cudaFuncAttributeMaxDynamicSharedMemorySize, 77888);
    cudaFuncSetAttribute(k_qkv_mma,  cudaFuncAttributeMaxDynamicSharedMemorySize, QKV_SMEM);
    cudaFuncSetAttribute(k_attn_mma, cudaFuncAttributeMaxDynamicSharedMemorySize, ATT_SMEM);
    cudaFuncSetAttribute(k_out_mma,  cudaFuncAttributeMaxDynamicSharedMemorySize, OUT_SMEM);

    k_down_rms<<<256, 192, 77888>>>(x, w_down, rms_w);
    k_pack_wup<<<(96 * NQKV + 255) / 256, 256>>>(w_up);
    k_pack_wo<<<(1536 * 1024 + 255) / 256, 256>>>(w_o);
    k_qkv_mma<<<dim3(32, 72), 256, QKV_SMEM>>>();
    k_attn_mma<<<dim3(16, 32), 256, ATT_SMEM>>>();
    k_out_mma<<<dim3(32, 8), 256, OUT_SMEM>>>(out);
}

// round 13
// speedup vs baseline: 1.3011x; 1.3011x over previous
#include <cuda_runtime.h>
#include <cuda_fp16.h>
#include <math.h>

#define SS 2048
#define HH 16
#define DM 1024
#define DH 192
#define NQKV 9216
#define DL 3072
#define BHN 32
#define MROWS 4096

// Scratch (device globals: no allocation allowed)
__device__ __half   g_hh[MROWS * DH];             // 1.5 MB half
// Q in A-fragment tile layout: [bh][tile64(32)][12ks][4ms][128]  (u32 = half2)
__device__ unsigned g_qf[BHN * 32 * 6144];        // 25 MB
// K in B-fragment tile layout: [bh][tile64(32)][12ks][8ns][64]
__device__ unsigned g_kf[BHN * 32 * 6144];        // 25 MB
// V in B-fragment tile layout (k=j, n=d): [bh][tile64(32)][4ks][24ns][64]
__device__ unsigned g_vf[BHN * 32 * 6144];        // 25 MB
// O in A-fragment tile layout: [b(2)][mt(16)][kc(48)][4ks][8ms][128]
__device__ unsigned g_attnf[2 * 16 * 48 * 4096];  // 25 MB
// w_up prepacked half B-frag: [nb(72)][12ks][16ns][64]
__device__ unsigned g_wu[72 * 12288];             // 3.5 MB
// w_o prepacked half B-frag: [nb(8)][kc(48)][4ks][16ns][64]
__device__ unsigned g_wo[8 * 48 * 4096];          // 6.3 MB

// ---------------------------------------------------------------------------
// f16 mma helpers (mma.sync m16n8k16, row.col, f32 accumulate)
//  A (16x16): (m,kp) -> [ks=k>>4][ms=m>>4][lane=(m&7)*4+(kp&3)][reg=((k&15)>=8)*2+((m&15)>=8)]
//  B (16x8):  (kp,n) -> [ks][ns=n>>3][lane=(n&7)*4+(kp&3)][reg=((k&15)>=8)]
//  Physical lane XOR-swizzled by slab: SW(lane, slab).
// ---------------------------------------------------------------------------
#define SW(l, s) ((l) ^ (((s) & 3) << 2))

__device__ __forceinline__ unsigned pack2(float a, float b) {
    __half2 h = __floats2half2_rn(a, b);
    return *(unsigned*)&h;
}

__device__ __forceinline__ void mma16(float4& d, const uint4& a, const uint2& b) {
    asm volatile("mma.sync.aligned.m16n8k16.row.col.f32.f16.f16.f32 "
                 "{%0,%1,%2,%3}, {%4,%5,%6,%7}, {%8,%9}, {%0,%1,%2,%3};\n"
                 : "+f"(d.x), "+f"(d.y), "+f"(d.z), "+f"(d.w)
                 : "r"(a.x), "r"(a.y), "r"(a.z), "r"(a.w), "r"(b.x), "r"(b.y));
}

__device__ __forceinline__ void cpa16(void* smem, const void* gmem) {
    unsigned sa = (unsigned)__cvta_generic_to_shared(smem);
    asm volatile("cp.async.cg.shared.global [%0], [%1], 16;" :: "r"(sa), "l"(gmem));
}
#define CP_COMMIT() asm volatile("cp.async.commit_group;")
#define CP_WAIT0()  asm volatile("cp.async.wait_group 0;")

// ---------------------------------------------------------------------------
// Kernel 1: h = rmsnorm(x @ w_down) * rms_w   -> g_hh (half)
// ---------------------------------------------------------------------------
__global__ void k_down_rms(const float* __restrict__ x,
                           const float* __restrict__ w_down,
                           const float* __restrict__ rms_w) {
    extern __shared__ float sm[];
    float* xs  = sm;                  // 16*1024
    float* red = sm + 16 * 1024;      // 16*192
    float* rs  = red + 16 * 192;      // 16

    int t  = threadIdx.x;             // 0..191
    int m0 = blockIdx.x * 16;

    const float4* xin = (const float4*)(x + (size_t)m0 * DM);
    float4* xs4 = (float4*)xs;
    for (int i = t; i < 16 * DM / 4; i += 192) xs4[i] = xin[i];
    __syncthreads();

    float acc[16];
#pragma unroll
    for (int r = 0; r < 16; r++) acc[r] = 0.f;

    for (int k = 0; k < DM; k += 4) {
        float w0 = w_down[(k + 0) * DH + t];
        float w1 = w_down[(k + 1) * DH + t];
        float w2 = w_down[(k + 2) * DH + t];
        float w3 = w_down[(k + 3) * DH + t];
#pragma unroll
        for (int r = 0; r < 16; r++) {
            float4 xv = *(const float4*)&xs[r * DM + k];
            acc[r] += xv.x * w0 + xv.y * w1 + xv.z * w2 + xv.w * w3;
        }
    }

#pragma unroll
    for (int r = 0; r < 16; r++) red[r * 192 + t] = acc[r] * acc[r];
    __syncthreads();
    for (int st = 96; st >= 3; st >>= 1) {
        if (t < st) {
#pragma unroll
            for (int r = 0; r < 16; r++) red[r * 192 + t] += red[r * 192 + t + st];
        }
        __syncthreads();
    }
    if (t < 16) {
        float s3 = red[t * 192 + 0] + red[t * 192 + 1] + red[t * 192 + 2];
        rs[t] = rsqrtf(s3 / 192.0f + 1e-6f);
    }
    __syncthreads();

    float w = rms_w[t];
#pragma unroll
    for (int r = 0; r < 16; r++)
        g_hh[(size_t)(m0 + r) * DH + t] = __float2half(acc[r] * rs[r] * w);
}

// ---------------------------------------------------------------------------
// Prepack kernels: weights -> half B-fragment tile layout (run per launch)
// ---------------------------------------------------------------------------
__global__ void k_pack_wup(const float* __restrict__ w_up) {
    int idx = blockIdx.x * 256 + threadIdx.x;     // 96*9216
    if (idx >= 96 * NQKV) return;
    int kp = idx / NQKV, n = idx % NQKV;
    int k = kp * 2;
    float v0 = w_up[(size_t)k * NQKV + n];
    float v1 = w_up[(size_t)(k + 1) * NQKV + n];
    int nb = n >> 7, nn = n & 127;
    int ks = k >> 4, reg = ((k & 15) >= 8) ? 1 : 0, c = (k & 7) >> 1;
    int ns = nn >> 3, l = (nn & 7) * 4 + c;
    g_wu[(size_t)nb * 12288 + (ks * 16 + ns) * 64 + SW(l, ns) * 2 + reg] = pack2(v0, v1);
}

__global__ void k_pack_wo(const float* __restrict__ w_o) {
    int idx = blockIdx.x * 256 + threadIdx.x;     // 1536*1024
    if (idx >= 1536 * 1024) return;
    int kp = idx >> 10, n = idx & 1023;
    int k = kp * 2;
    float v0 = w_o[(size_t)k * DM + n];
    float v1 = w_o[(size_t)(k + 1) * DM + n];
    int kc = k >> 6, kk = k & 63;
    int ks = kk >> 4, reg = ((kk & 15) >= 8) ? 1 : 0, c = (kk & 7) >> 1;
    int nb = n >> 7, nn = n & 127;
    int ns = nn >> 3, l = (nn & 7) * 4 + c;
    g_wo[(size_t)(nb * 48 + kc) * 4096 + (ks * 16 + ns) * 64 + SW(l, ns) * 2 + reg]
        = pack2(v0, v1);
}

// ---------------------------------------------------------------------------
// Kernel 2: qkv = h @ w_up (f16 mma). BM=128, BN=128, K=192. 256 threads,
// 8 warps 2(m) x 4(n); warp 64x32. B tile = raw cp.async copy of g_wu.
// RoPE fused into epilogue. n-derived scatter constants hoisted (4 distinct
// n values per thread, NOT 16 — kills the div/mod chain that showed alu=25%).
// ---------------------------------------------------------------------------
#define QKV_SMEM ((12 * 8 * 128 + 12 * 16 * 64) * 4)   // 98304 B
__global__ void __launch_bounds__(256, 2) k_qkv_mma() {
    extern __shared__ unsigned smu[];
    unsigned* Af = smu;                   // [12][8][128]
    unsigned* Bf = smu + 12288;           // [12][16][64]

    int tid = threadIdx.x, lane = tid & 31, warp = tid >> 5;
    int wm = warp >> 2, wn = warp & 3;
    int m0 = blockIdx.x * 128;
    int nb = blockIdx.y;                  // 0..71

    // B: raw async copy of prepacked w_up block
    {
        const uint4* wsrc = (const uint4*)(g_wu + (size_t)nb * 12288);
        uint4* Bd = (uint4*)Bf;
#pragma unroll
        for (int i = 0; i < 12; i++) cpa16(Bd + tid + i * 256, wsrc + tid + i * 256);
        CP_COMMIT();
    }
    // A: 128x192 halves of g_hh -> A-frag (k-pairs native)
    for (int i = tid; i < 128 * 48; i += 256) {
        int m = i / 48, k4 = (i % 48) * 4;
        uint2 v = *(const uint2*)&g_hh[(size_t)(m0 + m) * DH + k4];
        int ks = k4 >> 4, ms = m >> 4;
        int reg = (((k4 & 15) >= 8) ? 2 : 0) + (((m & 15) >= 8) ? 1 : 0);
        int l0 = (m & 7) * 4 + ((k4 >> 1) & 3);
        unsigned* base = &Af[(ks * 8 + ms) * 128];
        base[SW(l0, ms) * 4 + reg]     = v.x;
        base[SW(l0 + 1, ms) * 4 + reg] = v.y;
    }
    CP_WAIT0();
    __syncthreads();

    float4 acc[4][4];
#pragma unroll
    for (int im = 0; im < 4; im++)
#pragma unroll
        for (int in = 0; in < 4; in++) acc[im][in] = make_float4(0.f, 0.f, 0.f, 0.f);

#pragma unroll
    for (int ks = 0; ks < 12; ks++) {
        uint4 a[4];
#pragma unroll
        for (int im = 0; im < 4; im++) {
            int ms = wm * 4 + im;
            a[im] = *(const uint4*)&Af[(ks * 8 + ms) * 128 + SW(lane, ms) * 4];
        }
        uint2 b[4];
#pragma unroll
        for (int in = 0; in < 4; in++) {
            int ns = wn * 4 + in;
            b[in] = *(const uint2*)&Bf[(ks * 16 + ns) * 64 + SW(lane, ns) * 2];
        }
#pragma unroll
        for (int im = 0; im < 4; im++)
#pragma unroll
            for (int in = 0; in < 4; in++) mma16(acc[im][in], a[im], b[in]);
    }

    int b_ = m0 >> 11;
    int s0 = m0 & 2047;

    // hoisted n-derived scatter constants (4 distinct n per thread)
    int  pten[4], pbh[4], pd[4];
    bool prope[4];
    float pinv[4];
#pragma unroll
    for (int e = 0; e < 4; e++) {
        int in2 = e >> 1, cc = e & 1;
        int n = nb * 128 + wn * 32 + in2 * 8 + 2 * (lane & 3) + cc;
        int ten = n / 3072;
        int l = n % 3072;
        pten[e] = ten;
        int h_ = l & 15, d = l >> 4;
        pbh[e] = b_ * HH + h_;
        pd[e] = d;
        bool rope = (ten != 2) && ((unsigned)(d - 128) < 32u);
        prope[e] = rope;
        int p = (d - 128) >> 1;
        pinv[e] = rope ? exp2f(-(float)p * 0.8304820237218406f) : 0.f;  // ln-free
    }

#pragma unroll
    for (int im = 0; im < 4; im++)
#pragma unroll
        for (int h = 0; h < 2; h++) {
            int m = wm * 64 + im * 16 + h * 8 + (lane >> 2);
            int s = s0 + m;
            int tile = s >> 6, mrow = s & 63;
#pragma unroll
            for (int e = 0; e < 4; e++) {
                int in2 = e >> 1, cc = e & 1;
                float vlo, vhi;
                if (h) { vlo = cc ? acc[im][in2].w : acc[im][in2].z;
                         vhi = cc ? acc[im][in2 + 2].w : acc[im][in2 + 2].z; }
                else   { vlo = cc ? acc[im][in2].y : acc[im][in2].x;
                         vhi = cc ? acc[im][in2 + 2].y : acc[im][in2 + 2].x; }
                int ten = pten[e], d = pd[e], bh = pbh[e];
                if (prope[e]) {
                    float ang = (float)s * pinv[e];
                    float sn, cs;
                    sincosf(ang, &sn, &cs);
                    float t0 = vlo * cs - vhi * sn;
                    vhi = vhi * cs + vlo * sn;
                    vlo = t0;
                }
                if (ten == 2) {
                    // V: B-frag (k=j sequence, n=d); halves stored individually
                    int j = mrow;
                    size_t base = (size_t)(bh * 32 + tile) * 6144;
                    int ksv = j >> 4;
                    int regv = ((j & 15) >= 8) ? 1 : 0;
                    int cv = (j >> 1) & 3;
                    int ns0 = d >> 3;
                    int lf0 = (d & 7) * 4 + cv;
                    __half* vh = (__half*)g_vf;
                    vh[(base + (ksv * 24 + ns0) * 64 + SW(lf0, ns0) * 2 + regv) * 2 + (j & 1)]
                        = __float2half(vlo);
                    vh[(base + (ksv * 24 + ns0) * 64 + SW(lf0 + 4, ns0) * 2 + regv) * 2 + (j & 1)]
                        = __float2half(vhi);
                } else {
                    unsigned w = pack2(vlo, vhi);
                    int ks = d >> 4, c = (d & 7) >> 1;
                    int lf = (mrow & 7) * 4 + c;
                    if (ten == 0) {      // Q: A-frag
                        int ms = mrow >> 4;
                        int reg = (((d & 15) >= 8) ? 2 : 0) + (((mrow & 15) >= 8) ? 1 : 0);
                        g_qf[(size_t)(bh * 32 + tile) * 6144 +
                             (ks * 4 + ms) * 128 + SW(lf, ms) * 4 + reg] = w;
                    } else {             // K: B-frag
                        int ns = mrow >> 3;
                        int reg = ((d & 15) >= 8) ? 1 : 0;
                        g_kf[(size_t)(bh * 32 + tile) * 6144 +
                             (ks * 8 + ns) * 64 + SW(lf, ns) * 2 + reg] = w;
                    }
                }
            }
        }
}

// ---------------------------------------------------------------------------
// Kernel 4: causal flash attention (R10 design — the 295us measured one).
// Q tile 128 rows, 512 threads (16 warps, 4m x 4n). K/V double-buffered
// cp.async raw copies. Epilogue writes O in A-fragment tile layout.
// ---------------------------------------------------------------------------
#define ATT_SMEM ((12288 * 3 + 4096 + 512 + 512 + 256 + 256) * 4)   // 169984 B
__global__ void __launch_bounds__(512, 1) k_attn_mma() {
    extern __shared__ unsigned smu[];
    unsigned* Qf = smu;                    // [2 half][12ks][4ms][128]
    unsigned* Kf = smu + 12288;            // 2 x [12ks][8ns][64]
    unsigned* Vf = smu + 24576;            // 2 x [4ks][24ns][64]
    unsigned* Pf = smu + 36864;            // [4ks][8ms][128]
    float* redm = (float*)(smu + 40960);   // [128][4]
    float* reds = redm + 512;              // [128][4]
    float* rowm = reds + 512;              // [2][128]
    float* rowl = rowm + 256;              // [2][128]

    int tid = threadIdx.x, lane = tid & 31, warp = tid >> 5;
    int wm = warp >> 2, wn = warp & 3;
    int bh = blockIdx.y;
    int it = 15 - blockIdx.x;              // longest tiles first
    int i0 = it * 128;

    // prefetch Q (two contiguous 64-row frag tiles = 3072 uint4) + K/V tile 0
    {
        const uint4* qt4 = (const uint4*)(g_qf + (size_t)(bh * 32 + it * 2) * 6144);
        const uint4* kt4 = (const uint4*)(g_kf + (size_t)(bh * 32) * 6144);
        const uint4* vt4 = (const uint4*)(g_vf + (size_t)(bh * 32) * 6144);
        uint4* Qd = (uint4*)Qf;
        uint4* Kd = (uint4*)Kf;
        uint4* Vd = (uint4*)Vf;
#pragma unroll
        for (int i = 0; i < 6; i++) cpa16(Qd + tid + i * 512, qt4 + tid + i * 512);
#pragma unroll
        for (int i = 0; i < 3; i++) {
            cpa16(Kd + tid + i * 512, kt4 + tid + i * 512);
            cpa16(Vd + tid + i * 512, vt4 + tid + i * 512);
        }
        CP_COMMIT();
    }
    if (tid < 128) { rowm[tid] = -3.0e38f; rowl[tid] = 0.f; }

    float4 o[2][6];
#pragma unroll
    for (int im = 0; im < 2; im++)
#pragma unroll
        for (int in = 0; in < 6; in++) o[im][in] = make_float4(0.f, 0.f, 0.f, 0.f);

    const float scale = 0.07216878364870323f;   // 1/sqrt(192)
    int ntile = 2 * it + 2;

    for (int jt = 0; jt < ntile; jt++) {
        int par = jt & 1;
        int kb = par * 6144;
        bool diag = (jt >= 2 * it);
        int off = jt * 64 - i0;

        CP_WAIT0();
        __syncthreads();                     // tile data ready; prev compute done

        // prefetch next K/V tile into other buffer (overlaps with compute)
        if (jt + 1 < ntile) {
            const uint4* kt4 = (const uint4*)(g_kf + (size_t)(bh * 32 + jt + 1) * 6144);
            const uint4* vt4 = (const uint4*)(g_vf + (size_t)(bh * 32 + jt + 1) * 6144);
            uint4* Kd = (uint4*)(Kf + (kb ^ 6144));
            uint4* Vd = (uint4*)(Vf + (kb ^ 6144));
#pragma unroll
            for (int i = 0; i < 3; i++) {
                cpa16(Kd + tid + i * 512, kt4 + tid + i * 512);
                cpa16(Vd + tid + i * 512, vt4 + tid + i * 512);
            }
        }
        CP_COMMIT();

        // S = Q K^T : warp tile 32(m) x 16(n)
        float4 s[2][2];
#pragma unroll
        for (int im = 0; im < 2; im++)
#pragma unroll
            for (int in = 0; in < 2; in++) s[im][in] = make_float4(0.f, 0.f, 0.f, 0.f);

#pragma unroll
        for (int ks = 0; ks < 12; ks++) {
            uint4 a[2];
#pragma unroll
            for (int im = 0; im < 2; im++) {
                int msg = wm * 2 + im;
                a[im] = *(const uint4*)&Qf[(msg >> 2) * 6144 +
                                           (ks * 4 + (msg & 3)) * 128 + SW(lane, msg & 3) * 4];
            }
            uint2 b0 = *(const uint2*)&Kf[kb + (ks * 8 + wn * 2 + 0) * 64 + SW(lane, wn * 2) * 2];
            uint2 b1 = *(const uint2*)&Kf[kb + (ks * 8 + wn * 2 + 1) * 64 + SW(lane, wn * 2 + 1) * 2];
            mma16(s[0][0], a[0], b0); mma16(s[0][1], a[0], b1);
            mma16(s[1][0], a[1], b0); mma16(s[1][1], a[1], b1);
        }

        // scale + mask in place; per-row tile max
        float mx[2][2];
#pragma unroll
        for (int im = 0; im < 2; im++) { mx[im][0] = -3.0e38f; mx[im][1] = -3.0e38f; }
#pragma unroll
        for (int im = 0; im < 2; im++)
#pragma unroll
            for (int in = 0; in < 2; in++) {
                float4& sv = s[im][in];
                sv.x *= scale; sv.y *= scale; sv.z *= scale; sv.w *= scale;
                if (diag) {
                    int colb = off + wn * 16 + in * 8 + 2 * (lane & 3);
                    int r0 = wm * 32 + im * 16 + (lane >> 2);
                    if (colb > r0)     sv.x = -1e9f;
                    if (colb + 1 > r0) sv.y = -1e9f;
                    if (colb > r0 + 8)     sv.z = -1e9f;
                    if (colb + 1 > r0 + 8) sv.w = -1e9f;
                }
                mx[im][0] = fmaxf(mx[im][0], fmaxf(sv.x, sv.y));
                mx[im][1] = fmaxf(mx[im][1], fmaxf(sv.z, sv.w));
            }
#pragma unroll
        for (int im = 0; im < 2; im++)
#pragma unroll
            for (int h = 0; h < 2; h++) {
                float m_ = mx[im][h];
                m_ = fmaxf(m_, __shfl_xor_sync(0xffffffffu, m_, 1));
                m_ = fmaxf(m_, __shfl_xor_sync(0xffffffffu, m_, 2));
                if ((lane & 3) == 0) {
                    int row = wm * 32 + im * 16 + h * 8 + (lane >> 2);
                    redm[row * 4 + wn] = m_;
                }
            }
        __syncthreads();

        // exp in place + partial sums + P -> A-frag; new row-max to next parity
        float cloc[2][2];
#pragma unroll
        for (int im = 0; im < 2; im++)
#pragma unroll
            for (int h = 0; h < 2; h++) {
                int row = wm * 32 + im * 16 + h * 8 + (lane >> 2);
                float4 rp = *(const float4*)&redm[row * 4];
                float mo = rowm[par * 128 + row];
                float mn = fmaxf(fmaxf(fmaxf(rp.x, rp.y), fmaxf(rp.z, rp.w)), mo);
                cloc[im][h] = __expf(mo - mn);
                float ssum = 0.f;
                int msg = wm * 2 + im;
#pragma unroll
                for (int in = 0; in < 2; in++) {
                    float v0 = h ? s[im][in].z : s[im][in].x;
                    float v1 = h ? s[im][in].w : s[im][in].y;
                    float e0 = __expf(v0 - mn);
                    float e1 = __expf(v1 - mn);
                    ssum += e0 + e1;
                    Pf[(wn * 8 + msg) * 128 + SW(lane, msg & 3) * 4 + (in * 2 + h)] = pack2(e0, e1);
                }
                ssum += __shfl_xor_sync(0xffffffffu, ssum, 1);
                ssum += __shfl_xor_sync(0xffffffffu, ssum, 2);
                if ((lane & 3) == 0) {
                    reds[row * 4 + wn] = ssum;
                    if (wn == 0) rowm[(par ^ 1) * 128 + row] = mn;
                }
            }
        __syncthreads();

        // distributed row-sum update, rescale O, then O += P @ V
        if (wn == 0 && (lane & 3) == 0) {
#pragma unroll
            for (int im = 0; im < 2; im++)
#pragma unroll
                for (int h = 0; h < 2; h++) {
                    int row = wm * 32 + im * 16 + h * 8 + (lane >> 2);
                    float4 sp = *(const float4*)&reds[row * 4];
                    float ts = sp.x + sp.y + sp.z + sp.w;
                    rowl[(par ^ 1) * 128 + row] = rowl[par * 128 + row] * cloc[im][h] + ts;
                }
        }
#pragma unroll
        for (int im = 0; im < 2; im++)
#pragma unroll
            for (int in = 0; in < 6; in++) {
                o[im][in].x *= cloc[im][0]; o[im][in].y *= cloc[im][0];
                o[im][in].z *= cloc[im][1]; o[im][in].w *= cloc[im][1];
            }
#pragma unroll
        for (int ksP = 0; ksP < 4; ksP++) {
            uint4 a[2];
#pragma unroll
            for (int im = 0; im < 2; im++) {
                int msg = wm * 2 + im;
                a[im] = *(const uint4*)&Pf[(ksP * 8 + msg) * 128 + SW(lane, msg & 3) * 4];
            }
            uint2 b[6];
#pragma unroll
            for (int in = 0; in < 6; in++) {
                int ns = wn * 6 + in;
                b[in] = *(const uint2*)&Vf[kb + (ksP * 24 + ns) * 64 + SW(lane, ns) * 2];
            }
#pragma unroll
            for (int in = 0; in < 6; in++) { mma16(o[0][in], a[0], b[in]); mma16(o[1][in], a[1], b[in]); }
        }
    }
    __syncthreads();                             // final rowl visible

    // epilogue: normalize, write O in A-frag tile layout (g_attnf)
    int fpar = ntile & 1;
    int b_ = bh >> 4;
    int h_ = bh & 15;
    size_t tb = (size_t)(b_ * 16 + it) * 48 * 4096;
#pragma unroll
    for (int im = 0; im < 2; im++)
#pragma unroll
        for (int h = 0; h < 2; h++) {
            int row = wm * 32 + im * 16 + h * 8 + (lane >> 2);
            float inv = 1.f / rowl[fpar * 128 + row];
            int ms = row >> 4;
            int regm = ((row & 15) >= 8) ? 1 : 0;
#pragma unroll
            for (int in = 0; in < 6; in++) {
                int d = wn * 48 + in * 8 + 2 * (lane & 3);
                int l = h_ * 192 + d;
                int kc = l >> 6, kk = l & 63;
                int ks = kk >> 4;
                int regk = ((kk & 15) >= 8) ? 2 : 0;
                int c = (kk >> 1) & 3;
                int lw = (row & 7) * 4 + c;
                float vx = (h ? o[im][in].z : o[im][in].x) * inv;
                float vy = (h ? o[im][in].w : o[im][in].y) * inv;
                g_attnf[tb + ((kc * 4 + ks) * 8 + ms) * 128 + SW(lw, ms) * 4 + (regk + regm)]
                    = pack2(vx, vy);
            }
        }
}

// ---------------------------------------------------------------------------
// Kernel 5: out = O @ w_o  (f16 mma)  [4096,3072]@[3072,1024]
// BM=128, BN=128, BK=64, 48 chunks, double-buffered cp.async raw copies
// (A from g_attnf frag tiles, B from g_wo prepack). 8 warps 4m x 2n.
// ---------------------------------------------------------------------------
#define OUT_SMEM (2 * (4096 + 4096) * 4)   // 65536 B
__global__ void __launch_bounds__(256, 2) k_out_mma(float* __restrict__ out) {
    extern __shared__ unsigned smu[];
    unsigned* Af = smu;          // 2 x [4ks][8ms][128]
    unsigned* Bf = smu + 8192;   // 2 x [4ks][16ns][64]

    int tid = threadIdx.x, lane = tid & 31, warp = tid >> 5;
    int wm = warp >> 1, wn = warp & 1;
    int m0 = blockIdx.x * 128;
    int b_ = m0 >> 11, mt = (m0 >> 7) & 15;
    int nb = blockIdx.y;
    int n0 = nb * 128;

    const uint4* asrc = (const uint4*)(g_attnf + (size_t)(b_ * 16 + mt) * 48 * 4096);
    const uint4* bsrc = (const uint4*)(g_wo + (size_t)nb * 48 * 4096);

    {
        uint4* Ad = (uint4*)Af;
        uint4* Bd = (uint4*)Bf;
#pragma unroll
        for (int i = 0; i < 4; i++) {
            cpa16(Ad + tid + i * 256, asrc + tid + i * 256);
            cpa16(Bd + tid + i * 256, bsrc + tid + i * 256);
        }
        CP_COMMIT();
    }

    float4 acc[2][8];
#pragma unroll
    for (int im = 0; im < 2; im++)
#pragma unroll
        for (int in = 0; in < 8; in++) acc[im][in] = make_float4(0.f, 0.f, 0.f, 0.f);

    for (int kc = 0; kc < 48; kc++) {
        int boff = (kc & 1) * 4096;
        CP_WAIT0();
        __syncthreads();

        if (kc + 1 < 48) {
            int nboff = ((kc + 1) & 1) * 1024;
            uint4* Ad = (uint4*)Af + nboff;
            uint4* Bd = (uint4*)Bf + nboff;
            const uint4* an = asrc + (kc + 1) * 1024;
            const uint4* bn = bsrc + (kc + 1) * 1024;
#pragma unroll
            for (int i = 0; i < 4; i++) {
                cpa16(Ad + tid + i * 256, an + tid + i * 256);
                cpa16(Bd + tid + i * 256, bn + tid + i * 256);
            }
        }
        CP_COMMIT();

#pragma unroll
        for (int ks = 0; ks < 4; ks++) {
            uint4 a0 = *(const uint4*)&Af[boff + (ks * 8 + wm * 2 + 0) * 128 + SW(lane, wm * 2) * 4];
            uint4 a1 = *(const uint4*)&Af[boff + (ks * 8 + wm * 2 + 1) * 128 + SW(lane, wm * 2 + 1) * 4];
            uint2 b[8];
#pragma unroll
            for (int in = 0; in < 8; in++) {
                int ns = wn * 8 + in;
                b[in] = *(const uint2*)&Bf[boff + (ks * 16 + ns) * 64 + SW(lane, ns) * 2];
            }
#pragma unroll
            for (int in = 0; in < 8; in++) { mma16(acc[0][in], a0, b[in]); mma16(acc[1][in], a1, b[in]); }
        }
    }

#pragma unroll
    for (int im = 0; im < 2; im++)
#pragma unroll
        for (int h = 0; h < 2; h++) {
            int m = m0 + wm * 32 + im * 16 + h * 8 + (lane >> 2);
#pragma unroll
            for (int in = 0; in < 8; in++) {
                int n = n0 + wn * 64 + in * 8 + 2 * (lane & 3);
                float2 v;
                v.x = h ? acc[im][in].z : acc[im][in].x;
                v.y = h ? acc[im][in].w : acc[im][in].y;
                *(float2*)&out[(size_t)m * DM + n] = v;
            }
        }
}

// ---------------------------------------------------------------------------
extern "C" void kernel_launch(void* const* d_in, const int* in_sizes, int n_in,
                              void* d_out, int out_size) {
    (void)in_sizes; (void)n_in; (void)out_size;
    const float* x      = (const float*)d_in[0];
    // d_in[1] = mask (int32 tril) — causality applied analytically, ignored
    const float* w_down = (const float*)d_in[2];
    const float* rms_w  = (const float*)d_in[3];
    const float* w_up   = (const float*)d_in[4];
    const float* w_o    = (const float*)d_in[5];
    float* out = (float*)d_out;

    cudaFuncSetAttribute(k_down_rms, cudaFuncAttributeMaxDynamicSharedMemorySize, 77888);
    cudaFuncSetAttribute(k_qkv_mma,  cudaFuncAttributeMaxDynamicSharedMemorySize, QKV_SMEM);
    cudaFuncSetAttribute(k_attn_mma, cudaFuncAttributeMaxDynamicSharedMemorySize, ATT_SMEM);
    cudaFuncSetAttribute(k_out_mma,  cudaFuncAttributeMaxDynamicSharedMemorySize, OUT_SMEM);

    k_down_rms<<<256, 192, 77888>>>(x, w_down, rms_w);
    k_pack_wup<<<(96 * NQKV + 255) / 256, 256>>>(w_up);
    k_pack_wo<<<(1536 * 1024 + 255) / 256, 256>>>(w_o);
    k_qkv_mma<<<dim3(32, 72), 256, QKV_SMEM>>>();
    k_attn_mma<<<dim3(16, 32), 512, ATT_SMEM>>>();
    k_out_mma<<<dim3(32, 8), 256, OUT_SMEM>>>(out);
}

// round 14
// speedup vs baseline: 1.6038x; 1.2326x over previous
#include <cuda_runtime.h>
#include <cuda_fp16.h>
#include <math.h>

#define SS 2048
#define HH 16
#define DM 1024
#define DH 192
#define NQKV 9216
#define DL 3072
#define BHN 32
#define MROWS 4096

// Scratch (device globals: no allocation allowed)
__device__ __half   g_hh[MROWS * DH];             // 1.5 MB half
// Q in A-fragment tile layout: [bh][tile64(32)][12ks][4ms][128]  (u32 = half2)
__device__ unsigned g_qf[BHN * 32 * 6144];        // 25 MB
// K in B-fragment tile layout: [bh][tile64(32)][12ks][8ns][64]
__device__ unsigned g_kf[BHN * 32 * 6144];        // 25 MB
// V in B-fragment tile layout (k=j, n=d): [bh][tile64(32)][4ks][24ns][64]
__device__ unsigned g_vf[BHN * 32 * 6144];        // 25 MB
// O in A-fragment tile layout: [b(2)][mt(16)][kc(48)][4ks][8ms][128]
__device__ unsigned g_attnf[2 * 16 * 48 * 4096];  // 25 MB
// w_up prepacked half B-frag: [nb(72)][12ks][16ns][64]
__device__ unsigned g_wu[72 * 12288];             // 3.5 MB
// w_o prepacked half B-frag: [nb(8)][kc(48)][4ks][16ns][64]
__device__ unsigned g_wo[8 * 48 * 4096];          // 6.3 MB
// w_down prepacked tf32 B-frag: [kc(16)][ks(8)][ns(24)][32][2]
__device__ unsigned g_wd[16 * 8 * 24 * 64];       // 768 KB

// ---------------------------------------------------------------------------
// f16 mma helpers (mma.sync m16n8k16, row.col, f32 accumulate)
//  A (16x16): (m,kp) -> [ks=k>>4][ms=m>>4][lane=(m&7)*4+(kp&3)][reg=((k&15)>=8)*2+((m&15)>=8)]
//  B (16x8):  (kp,n) -> [ks][ns=n>>3][lane=(n&7)*4+(kp&3)][reg=((k&15)>=8)]
//  Physical lane XOR-swizzled by slab: SW(lane, slab).
// ---------------------------------------------------------------------------
#define SW(l, s) ((l) ^ (((s) & 3) << 2))

__device__ __forceinline__ unsigned pack2(float a, float b) {
    __half2 h = __floats2half2_rn(a, b);
    return *(unsigned*)&h;
}

__device__ __forceinline__ unsigned f2tf(float f) {
    unsigned u;
    asm("cvt.rna.tf32.f32 %0, %1;" : "=r"(u) : "f"(f));
    return u;
}

__device__ __forceinline__ void mma16(float4& d, const uint4& a, const uint2& b) {
    asm volatile("mma.sync.aligned.m16n8k16.row.col.f32.f16.f16.f32 "
                 "{%0,%1,%2,%3}, {%4,%5,%6,%7}, {%8,%9}, {%0,%1,%2,%3};\n"
                 : "+f"(d.x), "+f"(d.y), "+f"(d.z), "+f"(d.w)
                 : "r"(a.x), "r"(a.y), "r"(a.z), "r"(a.w), "r"(b.x), "r"(b.y));
}

__device__ __forceinline__ void mma8(float4& d, const uint4& a, const uint2& b) {
    asm volatile("mma.sync.aligned.m16n8k8.row.col.f32.tf32.tf32.f32 "
                 "{%0,%1,%2,%3}, {%4,%5,%6,%7}, {%8,%9}, {%0,%1,%2,%3};\n"
                 : "+f"(d.x), "+f"(d.y), "+f"(d.z), "+f"(d.w)
                 : "r"(a.x), "r"(a.y), "r"(a.z), "r"(a.w), "r"(b.x), "r"(b.y));
}

__device__ __forceinline__ void cpa16(void* smem, const void* gmem) {
    unsigned sa = (unsigned)__cvta_generic_to_shared(smem);
    asm volatile("cp.async.cg.shared.global [%0], [%1], 16;" :: "r"(sa), "l"(gmem));
}
#define CP_COMMIT() asm volatile("cp.async.commit_group;")
#define CP_WAIT0()  asm volatile("cp.async.wait_group 0;")

// ---------------------------------------------------------------------------
// Prepack kernels: weights -> fragment tile layouts (run per launch)
// ---------------------------------------------------------------------------
__global__ void k_pack_wd(const float* __restrict__ w_down) {
    int idx = blockIdx.x * 256 + threadIdx.x;     // 1024*192
    if (idx >= 1024 * 192) return;
    int k = idx / 192, n = idx - k * 192;
    unsigned t = f2tf(w_down[idx]);
    int kc = k >> 6, kk = k & 63;
    int ks = kk >> 3, reg = ((kk & 7) >= 4) ? 1 : 0;
    g_wd[(((kc * 8 + ks) * 24 + (n >> 3)) * 32 + (n & 7) * 4 + (kk & 3)) * 2 + reg] = t;
}

__global__ void k_pack_wup(const float* __restrict__ w_up) {
    int idx = blockIdx.x * 256 + threadIdx.x;     // 96*9216
    if (idx >= 96 * NQKV) return;
    int kp = idx / NQKV, n = idx % NQKV;
    int k = kp * 2;
    float v0 = w_up[(size_t)k * NQKV + n];
    float v1 = w_up[(size_t)(k + 1) * NQKV + n];
    int nb = n >> 7, nn = n & 127;
    int ks = k >> 4, reg = ((k & 15) >= 8) ? 1 : 0, c = (k & 7) >> 1;
    int ns = nn >> 3, l = (nn & 7) * 4 + c;
    g_wu[(size_t)nb * 12288 + (ks * 16 + ns) * 64 + SW(l, ns) * 2 + reg] = pack2(v0, v1);
}

__global__ void k_pack_wo(const float* __restrict__ w_o) {
    int idx = blockIdx.x * 256 + threadIdx.x;     // 1536*1024
    if (idx >= 1536 * 1024) return;
    int kp = idx >> 10, n = idx & 1023;
    int k = kp * 2;
    float v0 = w_o[(size_t)k * DM + n];
    float v1 = w_o[(size_t)(k + 1) * DM + n];
    int kc = k >> 6, kk = k & 63;
    int ks = kk >> 4, reg = ((kk & 15) >= 8) ? 1 : 0, c = (kk & 7) >> 1;
    int nb = n >> 7, nn = n & 127;
    int ns = nn >> 3, l = (nn & 7) * 4 + c;
    g_wo[(size_t)(nb * 48 + kc) * 4096 + (ks * 16 + ns) * 64 + SW(l, ns) * 2 + reg]
        = pack2(v0, v1);
}

// ---------------------------------------------------------------------------
// Kernel 1: h = rmsnorm(x @ w_down) * rms_w -> g_hh (half), via tf32 mma.
// BM=32, N=192 (full), K=1024 in 16 chunks of 64. 256 threads, 8 warps
// (each warp 32m x 24n, 3 B-frags). B = raw cp.async of g_wd; A transformed
// in-kernel. Double-buffered. rmsnorm epilogue warp-local + small smem red.
// ---------------------------------------------------------------------------
#define DOWN_SMEM ((2 * 2048 + 2 * 12288 + 256) * 4)   // 115712 B
#define AFILL(kc_, buf_) do {                                                   \
    _Pragma("unroll")                                                           \
    for (int i_ = 0; i_ < 2; i_++) {                                            \
        int idx_ = tid + i_ * 256;                                              \
        int m_ = idx_ & 31, kq_ = (idx_ >> 5) * 4;                              \
        float4 v_ = *(const float4*)&x[(size_t)(m0 + m_) * DM + (kc_) * 64 + kq_]; \
        int ks_ = kq_ >> 3;                                                     \
        int rb_ = (((kq_ & 7) >= 4) ? 2 : 0) + (((m_ & 15) >= 8) ? 1 : 0);      \
        unsigned* dst_ = &Af[(buf_) * 2048 + ((ks_ * 2 + (m_ >> 4)) * 32 + (m_ & 7) * 4) * 4 + rb_]; \
        dst_[0] = f2tf(v_.x); dst_[4] = f2tf(v_.y);                             \
        dst_[8] = f2tf(v_.z); dst_[12] = f2tf(v_.w);                            \
    }                                                                           \
} while (0)

__global__ void __launch_bounds__(256, 1) k_down_mma(const float* __restrict__ x,
                                                     const float* __restrict__ rms_w) {
    extern __shared__ unsigned smu[];
    unsigned* Af = smu;             // 2 x [8ks][2ms][32][4]
    unsigned* Bf = smu + 4096;      // 2 x [8ks][24ns][32][2]
    float* red = (float*)(smu + 4096 + 24576);   // [32][8]

    int tid = threadIdx.x, lane = tid & 31, warp = tid >> 5;   // warp = n-group
    int m0 = blockIdx.x * 32;

    // prefetch B chunk 0 + fill A chunk 0
    {
        const uint4* src = (const uint4*)g_wd;
        uint4* dst = (uint4*)Bf;
#pragma unroll
        for (int i = 0; i < 12; i++) cpa16(dst + tid + i * 256, src + tid + i * 256);
        CP_COMMIT();
    }
    AFILL(0, 0);

    float4 acc[2][3];
#pragma unroll
    for (int im = 0; im < 2; im++)
#pragma unroll
        for (int in = 0; in < 3; in++) acc[im][in] = make_float4(0.f, 0.f, 0.f, 0.f);

    for (int kc = 0; kc < 16; kc++) {
        int buf = kc & 1;
        CP_WAIT0();
        __syncthreads();
        if (kc + 1 < 16) {
            const uint4* src = (const uint4*)g_wd + (size_t)(kc + 1) * 3072;
            uint4* dst = (uint4*)(Bf + (buf ^ 1) * 12288);
#pragma unroll
            for (int i = 0; i < 12; i++) cpa16(dst + tid + i * 256, src + tid + i * 256);
            CP_COMMIT();
            AFILL(kc + 1, buf ^ 1);
        }
#pragma unroll
        for (int ks = 0; ks < 8; ks++) {
            uint4 a0 = *(const uint4*)&Af[buf * 2048 + ((ks * 2 + 0) * 32 + lane) * 4];
            uint4 a1 = *(const uint4*)&Af[buf * 2048 + ((ks * 2 + 1) * 32 + lane) * 4];
            uint2 b[3];
#pragma unroll
            for (int in = 0; in < 3; in++)
                b[in] = *(const uint2*)&Bf[buf * 12288 + ((ks * 24 + warp * 3 + in) * 32 + lane) * 2];
#pragma unroll
            for (int in = 0; in < 3; in++) { mma8(acc[0][in], a0, b[in]); mma8(acc[1][in], a1, b[in]); }
        }
    }

    // rmsnorm epilogue
    __syncthreads();
#pragma unroll
    for (int im = 0; im < 2; im++)
#pragma unroll
        for (int h = 0; h < 2; h++) {
            int row = im * 16 + h * 8 + (lane >> 2);
            float ss = 0.f;
#pragma unroll
            for (int in = 0; in < 3; in++) {
                float a = h ? acc[im][in].z : acc[im][in].x;
                float b = h ? acc[im][in].w : acc[im][in].y;
                ss += a * a + b * b;
            }
            ss += __shfl_xor_sync(0xffffffffu, ss, 1);
            ss += __shfl_xor_sync(0xffffffffu, ss, 2);
            if ((lane & 3) == 0) red[row * 8 + warp] = ss;
        }
    __syncthreads();
#pragma unroll
    for (int im = 0; im < 2; im++)
#pragma unroll
        for (int h = 0; h < 2; h++) {
            int row = im * 16 + h * 8 + (lane >> 2);
            float4 r0 = *(const float4*)&red[row * 8];
            float4 r1 = *(const float4*)&red[row * 8 + 4];
            float tot = r0.x + r0.y + r0.z + r0.w + r1.x + r1.y + r1.z + r1.w;
            float rs = rsqrtf(tot / 192.0f + 1e-6f);
#pragma unroll
            for (int in = 0; in < 3; in++) {
                int col = warp * 24 + in * 8 + 2 * (lane & 3);
                float a = (h ? acc[im][in].z : acc[im][in].x) * rs * rms_w[col];
                float b = (h ? acc[im][in].w : acc[im][in].y) * rs * rms_w[col + 1];
                *(__half2*)&g_hh[(size_t)(m0 + row) * DH + col] = __floats2half2_rn(a, b);
            }
        }
}

// ---------------------------------------------------------------------------
// Kernel 2: qkv = h @ w_up (f16 mma). BM=128, BN=128, K=192. 256 threads,
// 8 warps 2(m) x 4(n); warp 64x32. B tile = raw cp.async copy of g_wu.
// RoPE fused. Scatter addresses fully linearized: ten is CTA-uniform,
// d is WARP-uniform, so every store is base[e] + M[row] (1 IADD).
// ---------------------------------------------------------------------------
#define QKV_SMEM ((12 * 8 * 128 + 12 * 16 * 64) * 4)   // 98304 B
__global__ void __launch_bounds__(256, 2) k_qkv_mma() {
    extern __shared__ unsigned smu[];
    unsigned* Af = smu;                   // [12][8][128]
    unsigned* Bf = smu + 12288;           // [12][16][64]

    int tid = threadIdx.x, lane = tid & 31, warp = tid >> 5;
    int wm = warp >> 2, wn = warp & 3;
    int m0 = blockIdx.x * 128;
    int nb = blockIdx.y;                  // 0..71

    // B: raw async copy of prepacked w_up block
    {
        const uint4* wsrc = (const uint4*)(g_wu + (size_t)nb * 12288);
        uint4* Bd = (uint4*)Bf;
#pragma unroll
        for (int i = 0; i < 12; i++) cpa16(Bd + tid + i * 256, wsrc + tid + i * 256);
        CP_COMMIT();
    }
    // A: 128x192 halves of g_hh -> A-frag (k-pairs native)
    for (int i = tid; i < 128 * 48; i += 256) {
        int m = i / 48, k4 = (i % 48) * 4;
        uint2 v = *(const uint2*)&g_hh[(size_t)(m0 + m) * DH + k4];
        int ks = k4 >> 4, ms = m >> 4;
        int reg = (((k4 & 15) >= 8) ? 2 : 0) + (((m & 15) >= 8) ? 1 : 0);
        int l0 = (m & 7) * 4 + ((k4 >> 1) & 3);
        unsigned* base = &Af[(ks * 8 + ms) * 128];
        base[SW(l0, ms) * 4 + reg]     = v.x;
        base[SW(l0 + 1, ms) * 4 + reg] = v.y;
    }
    CP_WAIT0();
    __syncthreads();

    float4 acc[4][4];
#pragma unroll
    for (int im = 0; im < 4; im++)
#pragma unroll
        for (int in = 0; in < 4; in++) acc[im][in] = make_float4(0.f, 0.f, 0.f, 0.f);

#pragma unroll
    for (int ks = 0; ks < 12; ks++) {
        uint4 a[4];
#pragma unroll
        for (int im = 0; im < 4; im++) {
            int ms = wm * 4 + im;
            a[im] = *(const uint4*)&Af[(ks * 8 + ms) * 128 + SW(lane, ms) * 4];
        }
        uint2 b[4];
#pragma unroll
        for (int in = 0; in < 4; in++) {
            int ns = wn * 4 + in;
            b[in] = *(const uint2*)&Bf[(ks * 16 + ns) * 64 + SW(lane, ns) * 2];
        }
#pragma unroll
        for (int im = 0; im < 4; im++)
#pragma unroll
            for (int in = 0; in < 4; in++) mma16(acc[im][in], a[im], b[in]);
    }

    int b_ = m0 >> 11;
    int s0 = m0 & 2047;
    int tenu = nb / 24;
    int nbp = nb - tenu * 24;
    int d = nbp * 8 + wn * 2;            // warp-uniform even d; pair (d, d+1)

    bool ropeu = (tenu != 2) && ((unsigned)(d - 128) < 32u);
    float pinv = ropeu ? exp2f(-(float)((d - 128) >> 1) * 0.8304820237218406f) : 0.f;

    // per-e (head) bases; store addr = ebase[e] + M[row-derived]
    size_t ebase[4];
    int dUV = 0;
    if (tenu == 0) {
        unsigned UQ = (d >> 4) * 512 + ((d & 7) >> 1) * 4 + (((d & 15) >= 8) ? 2 : 0);
#pragma unroll
        for (int e = 0; e < 4; e++) {
            int h_ = (e >> 1) * 8 + 2 * (lane & 3) + (e & 1);
            ebase[e] = (size_t)(b_ * HH + h_) * 196608 + UQ;
        }
    } else if (tenu == 1) {
        unsigned UK = (d >> 4) * 512 + ((d & 7) >> 1) * 2 + (((d & 15) >= 8) ? 1 : 0);
#pragma unroll
        for (int e = 0; e < 4; e++) {
            int h_ = (e >> 1) * 8 + 2 * (lane & 3) + (e & 1);
            ebase[e] = (size_t)(b_ * HH + h_) * 196608 + UK;
        }
    } else {
        unsigned x4 = ((d >> 3) & 3) << 2;
        unsigned UV1 = (d >> 3) * 128 + (((d & 7) * 4) ^ x4) * 4;
        unsigned UV2 = (d >> 3) * 128 + ((((d & 7) * 4) + 4) ^ x4) * 4;
        dUV = (int)UV2 - (int)UV1;
#pragma unroll
        for (int e = 0; e < 4; e++) {
            int h_ = (e >> 1) * 8 + 2 * (lane & 3) + (e & 1);
            ebase[e] = (size_t)(b_ * HH + h_) * 393216 + UV1;   // half units
        }
    }

#pragma unroll
    for (int im = 0; im < 4; im++)
#pragma unroll
        for (int h = 0; h < 2; h++) {
            int m = wm * 64 + im * 16 + h * 8 + (lane >> 2);
            int s = s0 + m;
            int tile = s >> 6, mrow = s & 63;
            float sn = 0.f, cs = 1.f;
            if (ropeu) sincosf((float)s * pinv, &sn, &cs);
            if (tenu == 2) {
                unsigned MV = tile * 12288 + (mrow >> 4) * 3072 + ((mrow >> 1) & 3) * 4
                            + (((mrow & 15) >= 8) ? 2 : 0) + (mrow & 1);
                __half* vh = (__half*)g_vf;
#pragma unroll
                for (int e = 0; e < 4; e++) {
                    int in2 = e >> 1, cc = e & 1;
                    float vlo, vhi;
                    if (h) { vlo = cc ? acc[im][in2].w : acc[im][in2].z;
                             vhi = cc ? acc[im][in2 + 2].w : acc[im][in2 + 2].z; }
                    else   { vlo = cc ? acc[im][in2].y : acc[im][in2].x;
                             vhi = cc ? acc[im][in2 + 2].y : acc[im][in2 + 2].x; }
                    vh[ebase[e] + MV]       = __float2half(vlo);
                    vh[ebase[e] + MV + dUV] = __float2half(vhi);
                }
            } else {
                unsigned M;
                if (tenu == 0)
                    M = tile * 6144 + (mrow >> 4) * 128
                      + (((mrow & 7) * 4) ^ (((mrow >> 4) & 3) << 2)) * 4
                      + (((mrow & 15) >= 8) ? 1 : 0);
                else
                    M = tile * 6144 + (mrow >> 3) * 64
                      + (((mrow & 7) * 4) ^ (((mrow >> 3) & 3) << 2)) * 2;
                unsigned* dst = (tenu == 0) ? g_qf : g_kf;
#pragma unroll
                for (int e = 0; e < 4; e++) {
                    int in2 = e >> 1, cc = e & 1;
                    float vlo, vhi;
                    if (h) { vlo = cc ? acc[im][in2].w : acc[im][in2].z;
                             vhi = cc ? acc[im][in2 + 2].w : acc[im][in2 + 2].z; }
                    else   { vlo = cc ? acc[im][in2].y : acc[im][in2].x;
                             vhi = cc ? acc[im][in2 + 2].y : acc[im][in2 + 2].x; }
                    if (ropeu) {
                        float t0 = vlo * cs - vhi * sn;
                        vhi = vhi * cs + vlo * sn;
                        vlo = t0;
                    }
                    dst[ebase[e] + M] = pack2(vlo, vhi);
                }
            }
        }
}

// ---------------------------------------------------------------------------
// Kernel 4: causal flash attention (R10 design — the 295us measured one).
// Q tile 128 rows, 512 threads (16 warps, 4m x 4n). K/V double-buffered
// cp.async raw copies. Epilogue writes O in A-fragment tile layout.
// ---------------------------------------------------------------------------
#define ATT_SMEM ((12288 * 3 + 4096 + 512 + 512 + 256 + 256) * 4)   // 169984 B
__global__ void __launch_bounds__(512, 1) k_attn_mma() {
    extern __shared__ unsigned smu[];
    unsigned* Qf = smu;                    // [2 half][12ks][4ms][128]
    unsigned* Kf = smu + 12288;            // 2 x [12ks][8ns][64]
    unsigned* Vf = smu + 24576;            // 2 x [4ks][24ns][64]
    unsigned* Pf = smu + 36864;            // [4ks][8ms][128]
    float* redm = (float*)(smu + 40960);   // [128][4]
    float* reds = redm + 512;              // [128][4]
    float* rowm = reds + 512;              // [2][128]
    float* rowl = rowm + 256;              // [2][128]

    int tid = threadIdx.x, lane = tid & 31, warp = tid >> 5;
    int wm = warp >> 2, wn = warp & 3;
    int bh = blockIdx.y;
    int it = 15 - blockIdx.x;              // longest tiles first
    int i0 = it * 128;

    // prefetch Q (two contiguous 64-row frag tiles = 3072 uint4) + K/V tile 0
    {
        const uint4* qt4 = (const uint4*)(g_qf + (size_t)(bh * 32 + it * 2) * 6144);
        const uint4* kt4 = (const uint4*)(g_kf + (size_t)(bh * 32) * 6144);
        const uint4* vt4 = (const uint4*)(g_vf + (size_t)(bh * 32) * 6144);
        uint4* Qd = (uint4*)Qf;
        uint4* Kd = (uint4*)Kf;
        uint4* Vd = (uint4*)Vf;
#pragma unroll
        for (int i = 0; i < 6; i++) cpa16(Qd + tid + i * 512, qt4 + tid + i * 512);
#pragma unroll
        for (int i = 0; i < 3; i++) {
            cpa16(Kd + tid + i * 512, kt4 + tid + i * 512);
            cpa16(Vd + tid + i * 512, vt4 + tid + i * 512);
        }
        CP_COMMIT();
    }
    if (tid < 128) { rowm[tid] = -3.0e38f; rowl[tid] = 0.f; }

    float4 o[2][6];
#pragma unroll
    for (int im = 0; im < 2; im++)
#pragma unroll
        for (int in = 0; in < 6; in++) o[im][in] = make_float4(0.f, 0.f, 0.f, 0.f);

    const float scale = 0.07216878364870323f;   // 1/sqrt(192)
    int ntile = 2 * it + 2;

    for (int jt = 0; jt < ntile; jt++) {
        int par = jt & 1;
        int kb = par * 6144;
        bool diag = (jt >= 2 * it);
        int off = jt * 64 - i0;

        CP_WAIT0();
        __syncthreads();                     // tile data ready; prev compute done

        // prefetch next K/V tile into other buffer (overlaps with compute)
        if (jt + 1 < ntile) {
            const uint4* kt4 = (const uint4*)(g_kf + (size_t)(bh * 32 + jt + 1) * 6144);
            const uint4* vt4 = (const uint4*)(g_vf + (size_t)(bh * 32 + jt + 1) * 6144);
            uint4* Kd = (uint4*)(Kf + (kb ^ 6144));
            uint4* Vd = (uint4*)(Vf + (kb ^ 6144));
#pragma unroll
            for (int i = 0; i < 3; i++) {
                cpa16(Kd + tid + i * 512, kt4 + tid + i * 512);
                cpa16(Vd + tid + i * 512, vt4 + tid + i * 512);
            }
        }
        CP_COMMIT();

        // S = Q K^T : warp tile 32(m) x 16(n)
        float4 s[2][2];
#pragma unroll
        for (int im = 0; im < 2; im++)
#pragma unroll
            for (int in = 0; in < 2; in++) s[im][in] = make_float4(0.f, 0.f, 0.f, 0.f);

#pragma unroll
        for (int ks = 0; ks < 12; ks++) {
            uint4 a[2];
#pragma unroll
            for (int im = 0; im < 2; im++) {
                int msg = wm * 2 + im;
                a[im] = *(const uint4*)&Qf[(msg >> 2) * 6144 +
                                           (ks * 4 + (msg & 3)) * 128 + SW(lane, msg & 3) * 4];
            }
            uint2 b0 = *(const uint2*)&Kf[kb + (ks * 8 + wn * 2 + 0) * 64 + SW(lane, wn * 2) * 2];
            uint2 b1 = *(const uint2*)&Kf[kb + (ks * 8 + wn * 2 + 1) * 64 + SW(lane, wn * 2 + 1) * 2];
            mma16(s[0][0], a[0], b0); mma16(s[0][1], a[0], b1);
            mma16(s[1][0], a[1], b0); mma16(s[1][1], a[1], b1);
        }

        // scale + mask in place; per-row tile max
        float mx[2][2];
#pragma unroll
        for (int im = 0; im < 2; im++) { mx[im][0] = -3.0e38f; mx[im][1] = -3.0e38f; }
#pragma unroll
        for (int im = 0; im < 2; im++)
#pragma unroll
            for (int in = 0; in < 2; in++) {
                float4& sv = s[im][in];
                sv.x *= scale; sv.y *= scale; sv.z *= scale; sv.w *= scale;
                if (diag) {
                    int colb = off + wn * 16 + in * 8 + 2 * (lane & 3);
                    int r0 = wm * 32 + im * 16 + (lane >> 2);
                    if (colb > r0)     sv.x = -1e9f;
                    if (colb + 1 > r0) sv.y = -1e9f;
                    if (colb > r0 + 8)     sv.z = -1e9f;
                    if (colb + 1 > r0 + 8) sv.w = -1e9f;
                }
                mx[im][0] = fmaxf(mx[im][0], fmaxf(sv.x, sv.y));
                mx[im][1] = fmaxf(mx[im][1], fmaxf(sv.z, sv.w));
            }
#pragma unroll
        for (int im = 0; im < 2; im++)
#pragma unroll
            for (int h = 0; h < 2; h++) {
                float m_ = mx[im][h];
                m_ = fmaxf(m_, __shfl_xor_sync(0xffffffffu, m_, 1));
                m_ = fmaxf(m_, __shfl_xor_sync(0xffffffffu, m_, 2));
                if ((lane & 3) == 0) {
                    int row = wm * 32 + im * 16 + h * 8 + (lane >> 2);
                    redm[row * 4 + wn] = m_;
                }
            }
        __syncthreads();

        // exp in place + partial sums + P -> A-frag; new row-max to next parity
        float cloc[2][2];
#pragma unroll
        for (int im = 0; im < 2; im++)
#pragma unroll
            for (int h = 0; h < 2; h++) {
                int row = wm * 32 + im * 16 + h * 8 + (lane >> 2);
                float4 rp = *(const float4*)&redm[row * 4];
                float mo = rowm[par * 128 + row];
                float mn = fmaxf(fmaxf(fmaxf(rp.x, rp.y), fmaxf(rp.z, rp.w)), mo);
                cloc[im][h] = __expf(mo - mn);
                float ssum = 0.f;
                int msg = wm * 2 + im;
#pragma unroll
                for (int in = 0; in < 2; in++) {
                    float v0 = h ? s[im][in].z : s[im][in].x;
                    float v1 = h ? s[im][in].w : s[im][in].y;
                    float e0 = __expf(v0 - mn);
                    float e1 = __expf(v1 - mn);
                    ssum += e0 + e1;
                    Pf[(wn * 8 + msg) * 128 + SW(lane, msg & 3) * 4 + (in * 2 + h)] = pack2(e0, e1);
                }
                ssum += __shfl_xor_sync(0xffffffffu, ssum, 1);
                ssum += __shfl_xor_sync(0xffffffffu, ssum, 2);
                if ((lane & 3) == 0) {
                    reds[row * 4 + wn] = ssum;
                    if (wn == 0) rowm[(par ^ 1) * 128 + row] = mn;
                }
            }
        __syncthreads();

        // distributed row-sum update, rescale O, then O += P @ V
        if (wn == 0 && (lane & 3) == 0) {
#pragma unroll
            for (int im = 0; im < 2; im++)
#pragma unroll
                for (int h = 0; h < 2; h++) {
                    int row = wm * 32 + im * 16 + h * 8 + (lane >> 2);
                    float4 sp = *(const float4*)&reds[row * 4];
                    float ts = sp.x + sp.y + sp.z + sp.w;
                    rowl[(par ^ 1) * 128 + row] = rowl[par * 128 + row] * cloc[im][h] + ts;
                }
        }
#pragma unroll
        for (int im = 0; im < 2; im++)
#pragma unroll
            for (int in = 0; in < 6; in++) {
                o[im][in].x *= cloc[im][0]; o[im][in].y *= cloc[im][0];
                o[im][in].z *= cloc[im][1]; o[im][in].w *= cloc[im][1];
            }
#pragma unroll
        for (int ksP = 0; ksP < 4; ksP++) {
            uint4 a[2];
#pragma unroll
            for (int im = 0; im < 2; im++) {
                int msg = wm * 2 + im;
                a[im] = *(const uint4*)&Pf[(ksP * 8 + msg) * 128 + SW(lane, msg & 3) * 4];
            }
            uint2 b[6];
#pragma unroll
            for (int in = 0; in < 6; in++) {
                int ns = wn * 6 + in;
                b[in] = *(const uint2*)&Vf[kb + (ksP * 24 + ns) * 64 + SW(lane, ns) * 2];
            }
#pragma unroll
            for (int in = 0; in < 6; in++) { mma16(o[0][in], a[0], b[in]); mma16(o[1][in], a[1], b[in]); }
        }
    }
    __syncthreads();                             // final rowl visible

    // epilogue: normalize, write O in A-frag tile layout (g_attnf)
    int fpar = ntile & 1;
    int b_ = bh >> 4;
    int h_ = bh & 15;
    size_t tb = (size_t)(b_ * 16 + it) * 48 * 4096;
#pragma unroll
    for (int im = 0; im < 2; im++)
#pragma unroll
        for (int h = 0; h < 2; h++) {
            int row = wm * 32 + im * 16 + h * 8 + (lane >> 2);
            float inv = 1.f / rowl[fpar * 128 + row];
            int ms = row >> 4;
            int regm = ((row & 15) >= 8) ? 1 : 0;
#pragma unroll
            for (int in = 0; in < 6; in++) {
                int d = wn * 48 + in * 8 + 2 * (lane & 3);
                int l = h_ * 192 + d;
                int kc = l >> 6, kk = l & 63;
                int ks = kk >> 4;
                int regk = ((kk & 15) >= 8) ? 2 : 0;
                int c = (kk >> 1) & 3;
                int lw = (row & 7) * 4 + c;
                float vx = (h ? o[im][in].z : o[im][in].x) * inv;
                float vy = (h ? o[im][in].w : o[im][in].y) * inv;
                g_attnf[tb + ((kc * 4 + ks) * 8 + ms) * 128 + SW(lw, ms) * 4 + (regk + regm)]
                    = pack2(vx, vy);
            }
        }
}

// ---------------------------------------------------------------------------
// Kernel 5: out = O @ w_o  (f16 mma)  [4096,3072]@[3072,1024]
// BM=128, BN=128, BK=64, 48 chunks, double-buffered cp.async raw copies
// (A from g_attnf frag tiles, B from g_wo prepack). 8 warps 4m x 2n.
// ---------------------------------------------------------------------------
#define OUT_SMEM (2 * (4096 + 4096) * 4)   // 65536 B
__global__ void __launch_bounds__(256, 2) k_out_mma(float* __restrict__ out) {
    extern __shared__ unsigned smu[];
    unsigned* Af = smu;          // 2 x [4ks][8ms][128]
    unsigned* Bf = smu + 8192;   // 2 x [4ks][16ns][64]

    int tid = threadIdx.x, lane = tid & 31, warp = tid >> 5;
    int wm = warp >> 1, wn = warp & 1;
    int m0 = blockIdx.x * 128;
    int b_ = m0 >> 11, mt = (m0 >> 7) & 15;
    int nb = blockIdx.y;
    int n0 = nb * 128;

    const uint4* asrc = (const uint4*)(g_attnf + (size_t)(b_ * 16 + mt) * 48 * 4096);
    const uint4* bsrc = (const uint4*)(g_wo + (size_t)nb * 48 * 4096);

    {
        uint4* Ad = (uint4*)Af;
        uint4* Bd = (uint4*)Bf;
#pragma unroll
        for (int i = 0; i < 4; i++) {
            cpa16(Ad + tid + i * 256, asrc + tid + i * 256);
            cpa16(Bd + tid + i * 256, bsrc + tid + i * 256);
        }
        CP_COMMIT();
    }

    float4 acc[2][8];
#pragma unroll
    for (int im = 0; im < 2; im++)
#pragma unroll
        for (int in = 0; in < 8; in++) acc[im][in] = make_float4(0.f, 0.f, 0.f, 0.f);

    for (int kc = 0; kc < 48; kc++) {
        int boff = (kc & 1) * 4096;
        CP_WAIT0();
        __syncthreads();

        if (kc + 1 < 48) {
            int nboff = ((kc + 1) & 1) * 1024;
            uint4* Ad = (uint4*)Af + nboff;
            uint4* Bd = (uint4*)Bf + nboff;
            const uint4* an = asrc + (kc + 1) * 1024;
            const uint4* bn = bsrc + (kc + 1) * 1024;
#pragma unroll
            for (int i = 0; i < 4; i++) {
                cpa16(Ad + tid + i * 256, an + tid + i * 256);
                cpa16(Bd + tid + i * 256, bn + tid + i * 256);
            }
        }
        CP_COMMIT();

#pragma unroll
        for (int ks = 0; ks < 4; ks++) {
            uint4 a0 = *(const uint4*)&Af[boff + (ks * 8 + wm * 2 + 0) * 128 + SW(lane, wm * 2) * 4];
            uint4 a1 = *(const uint4*)&Af[boff + (ks * 8 + wm * 2 + 1) * 128 + SW(lane, wm * 2 + 1) * 4];
            uint2 b[8];
#pragma unroll
            for (int in = 0; in < 8; in++) {
                int ns = wn * 8 + in;
                b[in] = *(const uint2*)&Bf[boff + (ks * 16 + ns) * 64 + SW(lane, ns) * 2];
            }
#pragma unroll
            for (int in = 0; in < 8; in++) { mma16(acc[0][in], a0, b[in]); mma16(acc[1][in], a1, b[in]); }
        }
    }

#pragma unroll
    for (int im = 0; im < 2; im++)
#pragma unroll
        for (int h = 0; h < 2; h++) {
            int m = m0 + wm * 32 + im * 16 + h * 8 + (lane >> 2);
#pragma unroll
            for (int in = 0; in < 8; in++) {
                int n = n0 + wn * 64 + in * 8 + 2 * (lane & 3);
                float2 v;
                v.x = h ? acc[im][in].z : acc[im][in].x;
                v.y = h ? acc[im][in].w : acc[im][in].y;
                *(float2*)&out[(size_t)m * DM + n] = v;
            }
        }
}

// ---------------------------------------------------------------------------
extern "C" void kernel_launch(void* const* d_in, const int* in_sizes, int n_in,
                              void* d_out, int out_size) {
    (void)in_sizes; (void)n_in; (void)out_size;
    const float* x      = (const float*)d_in[0];
    // d_in[1] = mask (int32 tril) — causality applied analytically, ignored
    const float* w_down = (const float*)d_in[2];
    const float* rms_w  = (const float*)d_in[3];
    const float* w_up   = (const float*)d_in[4];
    const float* w_o    = (const float*)d_in[5];
    float* out = (float*)d_out;

    cudaFuncSetAttribute(k_down_mma, cudaFuncAttributeMaxDynamicSharedMemorySize, DOWN_SMEM);
    cudaFuncSetAttribute(k_qkv_mma,  cudaFuncAttributeMaxDynamicSharedMemorySize, QKV_SMEM);
    cudaFuncSetAttribute(k_attn_mma, cudaFuncAttributeMaxDynamicSharedMemorySize, ATT_SMEM);
    cudaFuncSetAttribute(k_out_mma,  cudaFuncAttributeMaxDynamicSharedMemorySize, OUT_SMEM);

    k_pack_wd<<<(1024 * 192 + 255) / 256, 256>>>(w_down);
    k_pack_wup<<<(96 * NQKV + 255) / 256, 256>>>(w_up);
    k_pack_wo<<<(1536 * 1024 + 255) / 256, 256>>>(w_o);
    k_down_mma<<<128, 256, DOWN_SMEM>>>(x, rms_w);
    k_qkv_mma<<<dim3(32, 72), 256, QKV_SMEM>>>();
    k_attn_mma<<<dim3(16, 32), 512, ATT_SMEM>>>();
    k_out_mma<<<dim3(32, 8), 256, OUT_SMEM>>>(out);
}

// round 16
// speedup vs baseline: 1.6313x; 1.0171x over previous
#include <cuda_runtime.h>
#include <cuda_fp16.h>
#include <math.h>

#define SS 2048
#define HH 16
#define DM 1024
#define DH 192
#define NQKV 9216
#define DL 3072
#define BHN 32
#define MROWS 4096

// Scratch (device globals: no allocation allowed)
__device__ __half   g_hh[MROWS * DH];             // 1.5 MB half
// Q in A-fragment tile layout: [bh][tile64(32)][12ks][4ms][128]  (u32 = half2)
__device__ unsigned g_qf[BHN * 32 * 6144];        // 25 MB
// K in B-fragment tile layout: [bh][tile64(32)][12ks][8ns][64]
__device__ unsigned g_kf[BHN * 32 * 6144];        // 25 MB
// V in B-fragment tile layout (k=j, n=d): [bh][tile64(32)][4ks][24ns][64]
__device__ unsigned g_vf[BHN * 32 * 6144];        // 25 MB
// O in A-fragment tile layout: [b(2)][mt(16)][kc(48)][4ks][8ms][128]
__device__ unsigned g_attnf[2 * 16 * 48 * 4096];  // 25 MB
// w_up prepacked half B-frag: [nb(72)][12ks][16ns][64]
__device__ unsigned g_wu[72 * 12288];             // 3.5 MB
// w_o prepacked half B-frag: [nb(8)][kc(48)][4ks][16ns][64]
__device__ unsigned g_wo[8 * 48 * 4096];          // 6.3 MB
// w_down prepacked tf32 B-frag: [kc(16)][ks(8)][ns(24)][32][2]
__device__ unsigned g_wd[16 * 8 * 24 * 64];       // 768 KB

// ---------------------------------------------------------------------------
// f16 mma helpers (mma.sync m16n8k16, row.col, f32 accumulate)
//  A (16x16): (m,kp) -> [ks=k>>4][ms=m>>4][lane=(m&7)*4+(kp&3)][reg=((k&15)>=8)*2+((m&15)>=8)]
//  B (16x8):  (kp,n) -> [ks][ns=n>>3][lane=(n&7)*4+(kp&3)][reg=((k&15)>=8)]
//  Physical lane XOR-swizzled by slab: SW(lane, slab).
// ---------------------------------------------------------------------------
#define SW(l, s) ((l) ^ (((s) & 3) << 2))

__device__ __forceinline__ unsigned pack2(float a, float b) {
    __half2 h = __floats2half2_rn(a, b);
    return *(unsigned*)&h;
}

__device__ __forceinline__ unsigned f2tf(float f) {
    unsigned u;
    asm("cvt.rna.tf32.f32 %0, %1;" : "=r"(u) : "f"(f));
    return u;
}

__device__ __forceinline__ void mma16(float4& d, const uint4& a, const uint2& b) {
    asm volatile("mma.sync.aligned.m16n8k16.row.col.f32.f16.f16.f32 "
                 "{%0,%1,%2,%3}, {%4,%5,%6,%7}, {%8,%9}, {%0,%1,%2,%3};\n"
                 : "+f"(d.x), "+f"(d.y), "+f"(d.z), "+f"(d.w)
                 : "r"(a.x), "r"(a.y), "r"(a.z), "r"(a.w), "r"(b.x), "r"(b.y));
}

__device__ __forceinline__ void mma8(float4& d, const uint4& a, const uint2& b) {
    asm volatile("mma.sync.aligned.m16n8k8.row.col.f32.tf32.tf32.f32 "
                 "{%0,%1,%2,%3}, {%4,%5,%6,%7}, {%8,%9}, {%0,%1,%2,%3};\n"
                 : "+f"(d.x), "+f"(d.y), "+f"(d.z), "+f"(d.w)
                 : "r"(a.x), "r"(a.y), "r"(a.z), "r"(a.w), "r"(b.x), "r"(b.y));
}

__device__ __forceinline__ void cpa16(void* smem, const void* gmem) {
    unsigned sa = (unsigned)__cvta_generic_to_shared(smem);
    asm volatile("cp.async.cg.shared.global [%0], [%1], 16;" :: "r"(sa), "l"(gmem));
}
#define CP_COMMIT() asm volatile("cp.async.commit_group;")
#define CP_WAIT0()  asm volatile("cp.async.wait_group 0;")

// ---------------------------------------------------------------------------
// Prepack kernels: weights -> fragment tile layouts (run per launch)
// ---------------------------------------------------------------------------
__global__ void k_pack_wd(const float* __restrict__ w_down) {
    int idx = blockIdx.x * 256 + threadIdx.x;     // 1024*192
    if (idx >= 1024 * 192) return;
    int k = idx / 192, n = idx - k * 192;
    unsigned t = f2tf(w_down[idx]);
    int kc = k >> 6, kk = k & 63;
    int ks = kk >> 3, reg = ((kk & 7) >= 4) ? 1 : 0;
    g_wd[(((kc * 8 + ks) * 24 + (n >> 3)) * 32 + (n & 7) * 4 + (kk & 3)) * 2 + reg] = t;
}

__global__ void k_pack_wup(const float* __restrict__ w_up) {
    int idx = blockIdx.x * 256 + threadIdx.x;     // 96*9216
    if (idx >= 96 * NQKV) return;
    int kp = idx / NQKV, n = idx % NQKV;
    int k = kp * 2;
    float v0 = w_up[(size_t)k * NQKV + n];
    float v1 = w_up[(size_t)(k + 1) * NQKV + n];
    int nb = n >> 7, nn = n & 127;
    int ks = k >> 4, reg = ((k & 15) >= 8) ? 1 : 0, c = (k & 7) >> 1;
    int ns = nn >> 3, l = (nn & 7) * 4 + c;
    g_wu[(size_t)nb * 12288 + (ks * 16 + ns) * 64 + SW(l, ns) * 2 + reg] = pack2(v0, v1);
}

__global__ void k_pack_wo(const float* __restrict__ w_o) {
    int idx = blockIdx.x * 256 + threadIdx.x;     // 1536*1024
    if (idx >= 1536 * 1024) return;
    int kp = idx >> 10, n = idx & 1023;
    int k = kp * 2;
    float v0 = w_o[(size_t)k * DM + n];
    float v1 = w_o[(size_t)(k + 1) * DM + n];
    int kc = k >> 6, kk = k & 63;
    int ks = kk >> 4, reg = ((kk & 15) >= 8) ? 1 : 0, c = (kk & 7) >> 1;
    int nb = n >> 7, nn = n & 127;
    int ns = nn >> 3, l = (nn & 7) * 4 + c;
    g_wo[(size_t)(nb * 48 + kc) * 4096 + (ks * 16 + ns) * 64 + SW(l, ns) * 2 + reg]
        = pack2(v0, v1);
}

// ---------------------------------------------------------------------------
// Kernel 1: h = rmsnorm(x @ w_down) * rms_w -> g_hh (half), via tf32 mma.
// BM=32, N=192 (full), K=1024 in 16 chunks of 64. 256 threads, 8 warps
// (each warp 32m x 24n, 3 B-frags). B = raw cp.async of g_wd; A transformed
// in-kernel. Double-buffered. rmsnorm epilogue warp-local + small smem red.
// ---------------------------------------------------------------------------
#define DOWN_SMEM ((2 * 2048 + 2 * 12288 + 256) * 4)   // 115712 B
#define AFILL(kc_, buf_) do {                                                   \
    _Pragma("unroll")                                                           \
    for (int i_ = 0; i_ < 2; i_++) {                                            \
        int idx_ = tid + i_ * 256;                                              \
        int m_ = idx_ & 31, kq_ = (idx_ >> 5) * 4;                              \
        float4 v_ = *(const float4*)&x[(size_t)(m0 + m_) * DM + (kc_) * 64 + kq_]; \
        int ks_ = kq_ >> 3;                                                     \
        int rb_ = (((kq_ & 7) >= 4) ? 2 : 0) + (((m_ & 15) >= 8) ? 1 : 0);      \
        unsigned* dst_ = &Af[(buf_) * 2048 + ((ks_ * 2 + (m_ >> 4)) * 32 + (m_ & 7) * 4) * 4 + rb_]; \
        dst_[0] = f2tf(v_.x); dst_[4] = f2tf(v_.y);                             \
        dst_[8] = f2tf(v_.z); dst_[12] = f2tf(v_.w);                            \
    }                                                                           \
} while (0)

__global__ void __launch_bounds__(256, 1) k_down_mma(const float* __restrict__ x,
                                                     const float* __restrict__ rms_w) {
    extern __shared__ unsigned smu[];
    unsigned* Af = smu;             // 2 x [8ks][2ms][32][4]
    unsigned* Bf = smu + 4096;      // 2 x [8ks][24ns][32][2]
    float* red = (float*)(smu + 4096 + 24576);   // [32][8]

    int tid = threadIdx.x, lane = tid & 31, warp = tid >> 5;   // warp = n-group
    int m0 = blockIdx.x * 32;

    // prefetch B chunk 0 + fill A chunk 0
    {
        const uint4* src = (const uint4*)g_wd;
        uint4* dst = (uint4*)Bf;
#pragma unroll
        for (int i = 0; i < 12; i++) cpa16(dst + tid + i * 256, src + tid + i * 256);
        CP_COMMIT();
    }
    AFILL(0, 0);

    float4 acc[2][3];
#pragma unroll
    for (int im = 0; im < 2; im++)
#pragma unroll
        for (int in = 0; in < 3; in++) acc[im][in] = make_float4(0.f, 0.f, 0.f, 0.f);

    for (int kc = 0; kc < 16; kc++) {
        int buf = kc & 1;
        CP_WAIT0();
        __syncthreads();
        if (kc + 1 < 16) {
            const uint4* src = (const uint4*)g_wd + (size_t)(kc + 1) * 3072;
            uint4* dst = (uint4*)(Bf + (buf ^ 1) * 12288);
#pragma unroll
            for (int i = 0; i < 12; i++) cpa16(dst + tid + i * 256, src + tid + i * 256);
            CP_COMMIT();
            AFILL(kc + 1, buf ^ 1);
        }
#pragma unroll
        for (int ks = 0; ks < 8; ks++) {
            uint4 a0 = *(const uint4*)&Af[buf * 2048 + ((ks * 2 + 0) * 32 + lane) * 4];
            uint4 a1 = *(const uint4*)&Af[buf * 2048 + ((ks * 2 + 1) * 32 + lane) * 4];
            uint2 b[3];
#pragma unroll
            for (int in = 0; in < 3; in++)
                b[in] = *(const uint2*)&Bf[buf * 12288 + ((ks * 24 + warp * 3 + in) * 32 + lane) * 2];
#pragma unroll
            for (int in = 0; in < 3; in++) { mma8(acc[0][in], a0, b[in]); mma8(acc[1][in], a1, b[in]); }
        }
    }

    // rmsnorm epilogue
    __syncthreads();
#pragma unroll
    for (int im = 0; im < 2; im++)
#pragma unroll
        for (int h = 0; h < 2; h++) {
            int row = im * 16 + h * 8 + (lane >> 2);
            float ss = 0.f;
#pragma unroll
            for (int in = 0; in < 3; in++) {
                float a = h ? acc[im][in].z : acc[im][in].x;
                float b = h ? acc[im][in].w : acc[im][in].y;
                ss += a * a + b * b;
            }
            ss += __shfl_xor_sync(0xffffffffu, ss, 1);
            ss += __shfl_xor_sync(0xffffffffu, ss, 2);
            if ((lane & 3) == 0) red[row * 8 + warp] = ss;
        }
    __syncthreads();
#pragma unroll
    for (int im = 0; im < 2; im++)
#pragma unroll
        for (int h = 0; h < 2; h++) {
            int row = im * 16 + h * 8 + (lane >> 2);
            float4 r0 = *(const float4*)&red[row * 8];
            float4 r1 = *(const float4*)&red[row * 8 + 4];
            float tot = r0.x + r0.y + r0.z + r0.w + r1.x + r1.y + r1.z + r1.w;
            float rs = rsqrtf(tot / 192.0f + 1e-6f);
#pragma unroll
            for (int in = 0; in < 3; in++) {
                int col = warp * 24 + in * 8 + 2 * (lane & 3);
                float a = (h ? acc[im][in].z : acc[im][in].x) * rs * rms_w[col];
                float b = (h ? acc[im][in].w : acc[im][in].y) * rs * rms_w[col + 1];
                *(__half2*)&g_hh[(size_t)(m0 + row) * DH + col] = __floats2half2_rn(a, b);
            }
        }
}

// ---------------------------------------------------------------------------
// Kernel 2: qkv = h @ w_up (f16 mma). BM=128, BN=128, K=192. 256 threads,
// 8 warps 2(m) x 4(n); warp 64x32. B tile = raw cp.async copy of g_wu.
// RoPE fused. Scatter addresses fully linearized: ten is CTA-uniform,
// d is WARP-uniform, so every store is base[e] + M[row] (1 IADD).
// ---------------------------------------------------------------------------
#define QKV_SMEM ((12 * 8 * 128 + 12 * 16 * 64) * 4)   // 98304 B
__global__ void __launch_bounds__(256, 2) k_qkv_mma() {
    extern __shared__ unsigned smu[];
    unsigned* Af = smu;                   // [12][8][128]
    unsigned* Bf = smu + 12288;           // [12][16][64]

    int tid = threadIdx.x, lane = tid & 31, warp = tid >> 5;
    int wm = warp >> 2, wn = warp & 3;
    int m0 = blockIdx.x * 128;
    int nb = blockIdx.y;                  // 0..71

    // B: raw async copy of prepacked w_up block
    {
        const uint4* wsrc = (const uint4*)(g_wu + (size_t)nb * 12288);
        uint4* Bd = (uint4*)Bf;
#pragma unroll
        for (int i = 0; i < 12; i++) cpa16(Bd + tid + i * 256, wsrc + tid + i * 256);
        CP_COMMIT();
    }
    // A: 128x192 halves of g_hh -> A-frag (k-pairs native)
    for (int i = tid; i < 128 * 48; i += 256) {
        int m = i / 48, k4 = (i % 48) * 4;
        uint2 v = *(const uint2*)&g_hh[(size_t)(m0 + m) * DH + k4];
        int ks = k4 >> 4, ms = m >> 4;
        int reg = (((k4 & 15) >= 8) ? 2 : 0) + (((m & 15) >= 8) ? 1 : 0);
        int l0 = (m & 7) * 4 + ((k4 >> 1) & 3);
        unsigned* base = &Af[(ks * 8 + ms) * 128];
        base[SW(l0, ms) * 4 + reg]     = v.x;
        base[SW(l0 + 1, ms) * 4 + reg] = v.y;
    }
    CP_WAIT0();
    __syncthreads();

    float4 acc[4][4];
#pragma unroll
    for (int im = 0; im < 4; im++)
#pragma unroll
        for (int in = 0; in < 4; in++) acc[im][in] = make_float4(0.f, 0.f, 0.f, 0.f);

#pragma unroll
    for (int ks = 0; ks < 12; ks++) {
        uint4 a[4];
#pragma unroll
        for (int im = 0; im < 4; im++) {
            int ms = wm * 4 + im;
            a[im] = *(const uint4*)&Af[(ks * 8 + ms) * 128 + SW(lane, ms) * 4];
        }
        uint2 b[4];
#pragma unroll
        for (int in = 0; in < 4; in++) {
            int ns = wn * 4 + in;
            b[in] = *(const uint2*)&Bf[(ks * 16 + ns) * 64 + SW(lane, ns) * 2];
        }
#pragma unroll
        for (int im = 0; im < 4; im++)
#pragma unroll
            for (int in = 0; in < 4; in++) mma16(acc[im][in], a[im], b[in]);
    }

    int b_ = m0 >> 11;
    int s0 = m0 & 2047;
    int tenu = nb / 24;
    int nbp = nb - tenu * 24;
    int d = nbp * 8 + wn * 2;            // warp-uniform even d; pair (d, d+1)

    bool ropeu = (tenu != 2) && ((unsigned)(d - 128) < 32u);
    float pinv = ropeu ? exp2f(-(float)((d - 128) >> 1) * 0.8304820237218406f) : 0.f;

    // per-e (head) bases; store addr = ebase[e] + M[row-derived]
    size_t ebase[4];
    int dUV = 0;
    if (tenu == 0) {
        unsigned UQ = (d >> 4) * 512 + ((d & 7) >> 1) * 4 + (((d & 15) >= 8) ? 2 : 0);
#pragma unroll
        for (int e = 0; e < 4; e++) {
            int h_ = (e >> 1) * 8 + 2 * (lane & 3) + (e & 1);
            ebase[e] = (size_t)(b_ * HH + h_) * 196608 + UQ;
        }
    } else if (tenu == 1) {
        unsigned UK = (d >> 4) * 512 + ((d & 7) >> 1) * 2 + (((d & 15) >= 8) ? 1 : 0);
#pragma unroll
        for (int e = 0; e < 4; e++) {
            int h_ = (e >> 1) * 8 + 2 * (lane & 3) + (e & 1);
            ebase[e] = (size_t)(b_ * HH + h_) * 196608 + UK;
        }
    } else {
        unsigned x4 = ((d >> 3) & 3) << 2;
        unsigned UV1 = (d >> 3) * 128 + (((d & 7) * 4) ^ x4) * 4;
        unsigned UV2 = (d >> 3) * 128 + ((((d & 7) * 4) + 4) ^ x4) * 4;
        dUV = (int)UV2 - (int)UV1;
#pragma unroll
        for (int e = 0; e < 4; e++) {
            int h_ = (e >> 1) * 8 + 2 * (lane & 3) + (e & 1);
            ebase[e] = (size_t)(b_ * HH + h_) * 393216 + UV1;   // half units
        }
    }

#pragma unroll
    for (int im = 0; im < 4; im++)
#pragma unroll
        for (int h = 0; h < 2; h++) {
            int m = wm * 64 + im * 16 + h * 8 + (lane >> 2);
            int s = s0 + m;
            int tile = s >> 6, mrow = s & 63;
            float sn = 0.f, cs = 1.f;
            if (ropeu) sincosf((float)s * pinv, &sn, &cs);
            if (tenu == 2) {
                unsigned MV = tile * 12288 + (mrow >> 4) * 3072 + ((mrow >> 1) & 3) * 4
                            + (((mrow & 15) >= 8) ? 2 : 0) + (mrow & 1);
                __half* vh = (__half*)g_vf;
#pragma unroll
                for (int e = 0; e < 4; e++) {
                    int in2 = e >> 1, cc = e & 1;
                    float vlo, vhi;
                    if (h) { vlo = cc ? acc[im][in2].w : acc[im][in2].z;
                             vhi = cc ? acc[im][in2 + 2].w : acc[im][in2 + 2].z; }
                    else   { vlo = cc ? acc[im][in2].y : acc[im][in2].x;
                             vhi = cc ? acc[im][in2 + 2].y : acc[im][in2 + 2].x; }
                    vh[ebase[e] + MV]       = __float2half(vlo);
                    vh[ebase[e] + MV + dUV] = __float2half(vhi);
                }
            } else {
                unsigned M;
                if (tenu == 0)
                    M = tile * 6144 + (mrow >> 4) * 128
                      + (((mrow & 7) * 4) ^ (((mrow >> 4) & 3) << 2)) * 4
                      + (((mrow & 15) >= 8) ? 1 : 0);
                else
                    M = tile * 6144 + (mrow >> 3) * 64
                      + (((mrow & 7) * 4) ^ (((mrow >> 3) & 3) << 2)) * 2;
                unsigned* dst = (tenu == 0) ? g_qf : g_kf;
#pragma unroll
                for (int e = 0; e < 4; e++) {
                    int in2 = e >> 1, cc = e & 1;
                    float vlo, vhi;
                    if (h) { vlo = cc ? acc[im][in2].w : acc[im][in2].z;
                             vhi = cc ? acc[im][in2 + 2].w : acc[im][in2 + 2].z; }
                    else   { vlo = cc ? acc[im][in2].y : acc[im][in2].x;
                             vhi = cc ? acc[im][in2 + 2].y : acc[im][in2 + 2].x; }
                    if (ropeu) {
                        float t0 = vlo * cs - vhi * sn;
                        vhi = vhi * cs + vlo * sn;
                        vlo = t0;
                    }
                    dst[ebase[e] + M] = pack2(vlo, vhi);
                }
            }
        }
}

// ---------------------------------------------------------------------------
// Kernel 4: causal flash attention (R10 structure). Q tile 128 rows, 512
// threads (16 warps, 4m x 4n). K/V double-buffered cp.async raw copies.
// NEW: softmax barriers are per-wm-group named barriers (bar.sync wm+1, 128)
// — redm/reds/rowm/rowl/Pf are all wm-partitioned, so only the 4 warps of a
// wm group need to sync there. Only the K/V fill barrier stays full-CTA.
// ---------------------------------------------------------------------------
#define ATT_SMEM ((12288 * 3 + 4096 + 512 + 512 + 256 + 256) * 4)   // 169984 B
#define BARWM() asm volatile("bar.sync %0, 128;" :: "r"(wm + 1) : "memory")
__global__ void __launch_bounds__(512, 1) k_attn_mma() {
    extern __shared__ unsigned smu[];
    unsigned* Qf = smu;                    // [2 half][12ks][4ms][128]
    unsigned* Kf = smu + 12288;            // 2 x [12ks][8ns][64]
    unsigned* Vf = smu + 24576;            // 2 x [4ks][24ns][64]
    unsigned* Pf = smu + 36864;            // [4ks][8ms][128]
    float* redm = (float*)(smu + 40960);   // [128][4]
    float* reds = redm + 512;              // [128][4]
    float* rowm = reds + 512;              // [2][128]
    float* rowl = rowm + 256;              // [2][128]

    int tid = threadIdx.x, lane = tid & 31, warp = tid >> 5;
    int wm = warp >> 2, wn = warp & 3;
    int bh = blockIdx.y;
    int it = 15 - blockIdx.x;              // longest tiles first
    int i0 = it * 128;

    // prefetch Q (two contiguous 64-row frag tiles = 3072 uint4) + K/V tile 0
    {
        const uint4* qt4 = (const uint4*)(g_qf + (size_t)(bh * 32 + it * 2) * 6144);
        const uint4* kt4 = (const uint4*)(g_kf + (size_t)(bh * 32) * 6144);
        const uint4* vt4 = (const uint4*)(g_vf + (size_t)(bh * 32) * 6144);
        uint4* Qd = (uint4*)Qf;
        uint4* Kd = (uint4*)Kf;
        uint4* Vd = (uint4*)Vf;
#pragma unroll
        for (int i = 0; i < 6; i++) cpa16(Qd + tid + i * 512, qt4 + tid + i * 512);
#pragma unroll
        for (int i = 0; i < 3; i++) {
            cpa16(Kd + tid + i * 512, kt4 + tid + i * 512);
            cpa16(Vd + tid + i * 512, vt4 + tid + i * 512);
        }
        CP_COMMIT();
    }
    if (tid < 128) { rowm[tid] = -3.0e38f; rowl[tid] = 0.f; }

    float4 o[2][6];
#pragma unroll
    for (int im = 0; im < 2; im++)
#pragma unroll
        for (int in = 0; in < 6; in++) o[im][in] = make_float4(0.f, 0.f, 0.f, 0.f);

    const float scale = 0.07216878364870323f;   // 1/sqrt(192)
    int ntile = 2 * it + 2;

    for (int jt = 0; jt < ntile; jt++) {
        int par = jt & 1;
        int kb = par * 6144;
        bool diag = (jt >= 2 * it);
        int off = jt * 64 - i0;

        CP_WAIT0();
        __syncthreads();                     // K/V tile ready (full CTA)

        // prefetch next K/V tile into other buffer (overlaps with compute)
        if (jt + 1 < ntile) {
            const uint4* kt4 = (const uint4*)(g_kf + (size_t)(bh * 32 + jt + 1) * 6144);
            const uint4* vt4 = (const uint4*)(g_vf + (size_t)(bh * 32 + jt + 1) * 6144);
            uint4* Kd = (uint4*)(Kf + (kb ^ 6144));
            uint4* Vd = (uint4*)(Vf + (kb ^ 6144));
#pragma unroll
            for (int i = 0; i < 3; i++) {
                cpa16(Kd + tid + i * 512, kt4 + tid + i * 512);
                cpa16(Vd + tid + i * 512, vt4 + tid + i * 512);
            }
        }
        CP_COMMIT();

        // S = Q K^T : warp tile 32(m) x 16(n)
        float4 s[2][2];
#pragma unroll
        for (int im = 0; im < 2; im++)
#pragma unroll
            for (int in = 0; in < 2; in++) s[im][in] = make_float4(0.f, 0.f, 0.f, 0.f);

#pragma unroll
        for (int ks = 0; ks < 12; ks++) {
            uint4 a[2];
#pragma unroll
            for (int im = 0; im < 2; im++) {
                int msg = wm * 2 + im;
                a[im] = *(const uint4*)&Qf[(msg >> 2) * 6144 +
                                           (ks * 4 + (msg & 3)) * 128 + SW(lane, msg & 3) * 4];
            }
            uint2 b0 = *(const uint2*)&Kf[kb + (ks * 8 + wn * 2 + 0) * 64 + SW(lane, wn * 2) * 2];
            uint2 b1 = *(const uint2*)&Kf[kb + (ks * 8 + wn * 2 + 1) * 64 + SW(lane, wn * 2 + 1) * 2];
            mma16(s[0][0], a[0], b0); mma16(s[0][1], a[0], b1);
            mma16(s[1][0], a[1], b0); mma16(s[1][1], a[1], b1);
        }

        // scale + mask in place; per-row tile max
        float mx[2][2];
#pragma unroll
        for (int im = 0; im < 2; im++) { mx[im][0] = -3.0e38f; mx[im][1] = -3.0e38f; }
#pragma unroll
        for (int im = 0; im < 2; im++)
#pragma unroll
            for (int in = 0; in < 2; in++) {
                float4& sv = s[im][in];
                sv.x *= scale; sv.y *= scale; sv.z *= scale; sv.w *= scale;
                if (diag) {
                    int colb = off + wn * 16 + in * 8 + 2 * (lane & 3);
                    int r0 = wm * 32 + im * 16 + (lane >> 2);
                    if (colb > r0)     sv.x = -1e9f;
                    if (colb + 1 > r0) sv.y = -1e9f;
                    if (colb > r0 + 8)     sv.z = -1e9f;
                    if (colb + 1 > r0 + 8) sv.w = -1e9f;
                }
                mx[im][0] = fmaxf(mx[im][0], fmaxf(sv.x, sv.y));
                mx[im][1] = fmaxf(mx[im][1], fmaxf(sv.z, sv.w));
            }
#pragma unroll
        for (int im = 0; im < 2; im++)
#pragma unroll
            for (int h = 0; h < 2; h++) {
                float m_ = mx[im][h];
                m_ = fmaxf(m_, __shfl_xor_sync(0xffffffffu, m_, 1));
                m_ = fmaxf(m_, __shfl_xor_sync(0xffffffffu, m_, 2));
                if ((lane & 3) == 0) {
                    int row = wm * 32 + im * 16 + h * 8 + (lane >> 2);
                    redm[row * 4 + wn] = m_;
                }
            }
        BARWM();                              // wm-group sync (redm ready)

        // exp in place + partial sums + P -> A-frag; new row-max to next parity
        float cloc[2][2];
#pragma unroll
        for (int im = 0; im < 2; im++)
#pragma unroll
            for (int h = 0; h < 2; h++) {
                int row = wm * 32 + im * 16 + h * 8 + (lane >> 2);
                float4 rp = *(const float4*)&redm[row * 4];
                float mo = rowm[par * 128 + row];
                float mn = fmaxf(fmaxf(fmaxf(rp.x, rp.y), fmaxf(rp.z, rp.w)), mo);
                cloc[im][h] = __expf(mo - mn);
                float ssum = 0.f;
                int msg = wm * 2 + im;
#pragma unroll
                for (int in = 0; in < 2; in++) {
                    float v0 = h ? s[im][in].z : s[im][in].x;
                    float v1 = h ? s[im][in].w : s[im][in].y;
                    float e0 = __expf(v0 - mn);
                    float e1 = __expf(v1 - mn);
                    ssum += e0 + e1;
                    Pf[(wn * 8 + msg) * 128 + SW(lane, msg & 3) * 4 + (in * 2 + h)] = pack2(e0, e1);
                }
                ssum += __shfl_xor_sync(0xffffffffu, ssum, 1);
                ssum += __shfl_xor_sync(0xffffffffu, ssum, 2);
                if ((lane & 3) == 0) {
                    reds[row * 4 + wn] = ssum;
                    if (wn == 0) rowm[(par ^ 1) * 128 + row] = mn;
                }
            }
        BARWM();                              // wm-group sync (Pf/reds ready)

        // distributed row-sum update, rescale O, then O += P @ V
        if (wn == 0 && (lane & 3) == 0) {
#pragma unroll
            for (int im = 0; im < 2; im++)
#pragma unroll
                for (int h = 0; h < 2; h++) {
                    int row = wm * 32 + im * 16 + h * 8 + (lane >> 2);
                    float4 sp = *(const float4*)&reds[row * 4];
                    float ts = sp.x + sp.y + sp.z + sp.w;
                    rowl[(par ^ 1) * 128 + row] = rowl[par * 128 + row] * cloc[im][h] + ts;
                }
        }
#pragma unroll
        for (int im = 0; im < 2; im++)
#pragma unroll
            for (int in = 0; in < 6; in++) {
                o[im][in].x *= cloc[im][0]; o[im][in].y *= cloc[im][0];
                o[im][in].z *= cloc[im][1]; o[im][in].w *= cloc[im][1];
            }
#pragma unroll
        for (int ksP = 0; ksP < 4; ksP++) {
            uint4 a[2];
#pragma unroll
            for (int im = 0; im < 2; im++) {
                int msg = wm * 2 + im;
                a[im] = *(const uint4*)&Pf[(ksP * 8 + msg) * 128 + SW(lane, msg & 3) * 4];
            }
            uint2 b[6];
#pragma unroll
            for (int in = 0; in < 6; in++) {
                int ns = wn * 6 + in;
                b[in] = *(const uint2*)&Vf[kb + (ksP * 24 + ns) * 64 + SW(lane, ns) * 2];
            }
#pragma unroll
            for (int in = 0; in < 6; in++) { mma16(o[0][in], a[0], b[in]); mma16(o[1][in], a[1], b[in]); }
        }
    }
    __syncthreads();                             // final rowl visible

    // epilogue: normalize, write O in A-frag tile layout (g_attnf)
    int fpar = ntile & 1;
    int b_ = bh >> 4;
    int h_ = bh & 15;
    size_t tb = (size_t)(b_ * 16 + it) * 48 * 4096;
#pragma unroll
    for (int im = 0; im < 2; im++)
#pragma unroll
        for (int h = 0; h < 2; h++) {
            int row = wm * 32 + im * 16 + h * 8 + (lane >> 2);
            float inv = 1.f / rowl[fpar * 128 + row];
            int ms = row >> 4;
            int regm = ((row & 15) >= 8) ? 1 : 0;
#pragma unroll
            for (int in = 0; in < 6; in++) {
                int d = wn * 48 + in * 8 + 2 * (lane & 3);
                int l = h_ * 192 + d;
                int kc = l >> 6, kk = l & 63;
                int ks = kk >> 4;
                int regk = ((kk & 15) >= 8) ? 2 : 0;
                int c = (kk >> 1) & 3;
                int lw = (row & 7) * 4 + c;
                float vx = (h ? o[im][in].z : o[im][in].x) * inv;
                float vy = (h ? o[im][in].w : o[im][in].y) * inv;
                g_attnf[tb + ((kc * 4 + ks) * 8 + ms) * 128 + SW(lw, ms) * 4 + (regk + regm)]
                    = pack2(vx, vy);
            }
        }
}

// ---------------------------------------------------------------------------
// Kernel 5: out = O @ w_o  (f16 mma)  [4096,3072]@[3072,1024]
// BM=128, BN=128, BK=64, 48 chunks, double-buffered cp.async raw copies
// (A from g_attnf frag tiles, B from g_wo prepack). 8 warps 4m x 2n.
// ---------------------------------------------------------------------------
#define OUT_SMEM (2 * (4096 + 4096) * 4)   // 65536 B
__global__ void __launch_bounds__(256, 2) k_out_mma(float* __restrict__ out) {
    extern __shared__ unsigned smu[];
    unsigned* Af = smu;          // 2 x [4ks][8ms][128]
    unsigned* Bf = smu + 8192;   // 2 x [4ks][16ns][64]

    int tid = threadIdx.x, lane = tid & 31, warp = tid >> 5;
    int wm = warp >> 1, wn = warp & 1;
    int m0 = blockIdx.x * 128;
    int b_ = m0 >> 11, mt = (m0 >> 7) & 15;
    int nb = blockIdx.y;
    int n0 = nb * 128;

    const uint4* asrc = (const uint4*)(g_attnf + (size_t)(b_ * 16 + mt) * 48 * 4096);
    const uint4* bsrc = (const uint4*)(g_wo + (size_t)nb * 48 * 4096);

    {
        uint4* Ad = (uint4*)Af;
        uint4* Bd = (uint4*)Bf;
#pragma unroll
        for (int i = 0; i < 4; i++) {
            cpa16(Ad + tid + i * 256, asrc + tid + i * 256);
            cpa16(Bd + tid + i * 256, bsrc + tid + i * 256);
        }
        CP_COMMIT();
    }

    float4 acc[2][8];
#pragma unroll
    for (int im = 0; im < 2; im++)
#pragma unroll
        for (int in = 0; in < 8; in++) acc[im][in] = make_float4(0.f, 0.f, 0.f, 0.f);

    for (int kc = 0; kc < 48; kc++) {
        int boff = (kc & 1) * 4096;
        CP_WAIT0();
        __syncthreads();

        if (kc + 1 < 48) {
            int nboff = ((kc + 1) & 1) * 1024;
            uint4* Ad = (uint4*)Af + nboff;
            uint4* Bd = (uint4*)Bf + nboff;
            const uint4* an = asrc + (kc + 1) * 1024;
            const uint4* bn = bsrc + (kc + 1) * 1024;
#pragma unroll
            for (int i = 0; i < 4; i++) {
                cpa16(Ad + tid + i * 256, an + tid + i * 256);
                cpa16(Bd + tid + i * 256, bn + tid + i * 256);
            }
        }
        CP_COMMIT();

#pragma unroll
        for (int ks = 0; ks < 4; ks++) {
            uint4 a0 = *(const uint4*)&Af[boff + (ks * 8 + wm * 2 + 0) * 128 + SW(lane, wm * 2) * 4];
            uint4 a1 = *(const uint4*)&Af[boff + (ks * 8 + wm * 2 + 1) * 128 + SW(lane, wm * 2 + 1) * 4];
            uint2 b[8];
#pragma unroll
            for (int in = 0; in < 8; in++) {
                int ns = wn * 8 + in;
                b[in] = *(const uint2*)&Bf[boff + (ks * 16 + ns) * 64 + SW(lane, ns) * 2];
            }
#pragma unroll
            for (int in = 0; in < 8; in++) { mma16(acc[0][in], a0, b[in]); mma16(acc[1][in], a1, b[in]); }
        }
    }

#pragma unroll
    for (int im = 0; im < 2; im++)
#pragma unroll
        for (int h = 0; h < 2; h++) {
            int m = m0 + wm * 32 + im * 16 + h * 8 + (lane >> 2);
#pragma unroll
            for (int in = 0; in < 8; in++) {
                int n = n0 + wn * 64 + in * 8 + 2 * (lane & 3);
                float2 v;
                v.x = h ? acc[im][in].z : acc[im][in].x;
                v.y = h ? acc[im][in].w : acc[im][in].y;
                *(float2*)&out[(size_t)m * DM + n] = v;
            }
        }
}

// ---------------------------------------------------------------------------
extern "C" void kernel_launch(void* const* d_in, const int* in_sizes, int n_in,
                              void* d_out, int out_size) {
    (void)in_sizes; (void)n_in; (void)out_size;
    const float* x      = (const float*)d_in[0];
    // d_in[1] = mask (int32 tril) — causality applied analytically, ignored
    const float* w_down = (const float*)d_in[2];
    const float* rms_w  = (const float*)d_in[3];
    const float* w_up   = (const float*)d_in[4];
    const float* w_o    = (const float*)d_in[5];
    float* out = (float*)d_out;

    cudaFuncSetAttribute(k_down_mma, cudaFuncAttributeMaxDynamicSharedMemorySize, DOWN_SMEM);
    cudaFuncSetAttribute(k_qkv_mma,  cudaFuncAttributeMaxDynamicSharedMemorySize, QKV_SMEM);
    cudaFuncSetAttribute(k_attn_mma, cudaFuncAttributeMaxDynamicSharedMemorySize, ATT_SMEM);
    cudaFuncSetAttribute(k_out_mma,  cudaFuncAttributeMaxDynamicSharedMemorySize, OUT_SMEM);

    k_pack_wd<<<(1024 * 192 + 255) / 256, 256>>>(w_down);
    k_pack_wup<<<(96 * NQKV + 255) / 256, 256>>>(w_up);
    k_pack_wo<<<(1536 * 1024 + 255) / 256, 256>>>(w_o);
    k_down_mma<<<128, 256, DOWN_SMEM>>>(x, rms_w);
    k_qkv_mma<<<dim3(32, 72), 256, QKV_SMEM>>>();
    k_attn_mma<<<dim3(16, 32), 512, ATT_SMEM>>>();
    k_out_mma<<<dim3(32, 8), 256, OUT_SMEM>>>(out);
}